// round 9
// baseline (speedup 1.0000x reference)
#include <cuda_runtime.h>
#include <cuda_bf16.h>
#include <cstdint>

#define B_   64
#define L_   32
#define T_   31
#define V_   16000
#define ENC_ 512
#define DEC_ 512
#define ATT_ 512
#define EMB_ 256
#define P_   256

#define NB_    128   // persistent kernel blocks
#define GKS_   4     // gates split-K factor
#define MROWS_FC 2048

// ---------------- device scratch ----------------
__device__ float g_state[B_ * 1024];
__device__ float g_meanenc[B_ * ENC_];
__device__ float g_att1[B_ * P_ * ATT_];
__device__ float g_Wab[1024 * 512];
__device__ float g_bab[1024];
__device__ float g_Winit[1024 * 512];
__device__ float g_binit[1024];
__device__ float g_Wlstm[2048 * 1280];
__device__ float g_blstm[2048];
__device__ float g_ab[B_ * 1024];
__device__ float g_xinh[B_ * 1280];
__device__ float g_gp[GKS_ * B_ * 2048];
__device__ float g_hall[T_ * B_ * DEC_];
__device__ int   g_list[T_ * B_];
__device__ int   g_nact;
__device__ unsigned g_bar_count = 0;
__device__ unsigned g_bar_gen   = 0;

// bf16 hi/lo planes
__device__ __nv_bfloat16 g_enc_hi[B_ * P_ * ENC_];
__device__ __nv_bfloat16 g_enc_lo[B_ * P_ * ENC_];
__device__ __nv_bfloat16 g_Wenc_hi[ATT_ * ENC_];
__device__ __nv_bfloat16 g_Wenc_lo[ATT_ * ENC_];
__device__ __nv_bfloat16 g_Wfc_hi[V_ * DEC_];
__device__ __nv_bfloat16 g_Wfc_lo[V_ * DEC_];
__device__ __nv_bfloat16 g_Afc_hi[MROWS_FC * DEC_];
__device__ __nv_bfloat16 g_Afc_lo[MROWS_FC * DEC_];

__device__ __forceinline__ float4 ldcg4(const float* p) {
    return __ldcg(reinterpret_cast<const float4*>(p));
}
__device__ __forceinline__ uint32_t smem_u32(const void* p) {
    uint32_t a;
    asm("{ .reg .u64 t; cvta.to.shared.u64 t, %1; cvt.u32.u64 %0, t; }"
        : "=r"(a) : "l"(p));
    return a;
}
__device__ __forceinline__ void ldm_x4(uint32_t* r, uint32_t addr) {
    asm volatile("ldmatrix.sync.aligned.m8n8.x4.shared.b16 {%0,%1,%2,%3}, [%4];"
                 : "=r"(r[0]), "=r"(r[1]), "=r"(r[2]), "=r"(r[3]) : "r"(addr));
}
__device__ __forceinline__ void mma_bf16(float* c, const uint32_t* a, const uint32_t* b) {
    asm volatile(
        "mma.sync.aligned.m16n8k16.row.col.f32.bf16.bf16.f32 "
        "{%0,%1,%2,%3}, {%4,%5,%6,%7}, {%8,%9}, {%0,%1,%2,%3};"
        : "+f"(c[0]), "+f"(c[1]), "+f"(c[2]), "+f"(c[3])
        : "r"(a[0]), "r"(a[1]), "r"(a[2]), "r"(a[3]), "r"(b[0]), "r"(b[1]));
}

// ============ HMMA bf16-split GEMM: C = A*W^T + bias ============
// A planes: [Mrows x 512] bf16 row-major; B planes: [Nrows x 512] bf16.
// 128x128 tile, 8 warps (4 m x 2 n), BK=32, double-buffered.
// mode 0: direct write to outp + m*ldout + n  (att1)
// mode 1: rows gathered via g_list, masked by g_nact  (fc)
#define SST 40   // smem row stride in bf16 (32 + 8 pad)
__global__ __launch_bounds__(256) void mma_gemm_kernel(
    const __nv_bfloat16* __restrict__ Ahi, const __nv_bfloat16* __restrict__ Alo,
    const __nv_bfloat16* __restrict__ Bhi, const __nv_bfloat16* __restrict__ Blo,
    const float* __restrict__ bias, float* __restrict__ outp,
    int ldout, int mode)
{
    const int m0 = blockIdx.y * 128;
    const int n0 = blockIdx.x * 128;
    if (mode == 1 && m0 >= g_nact) return;

    __shared__ __align__(16) __nv_bfloat16 sA[2][128 * SST];
    __shared__ __align__(16) __nv_bfloat16 sB[2][128 * SST];

    const int tid = threadIdx.x;
    const int lane = tid & 31, wid = tid >> 5;
    const int wm = (wid & 3) * 32;
    const int wn = (wid >> 2) * 64;

    float c[2][8][4];
#pragma unroll
    for (int i = 0; i < 2; i++)
#pragma unroll
        for (int j = 0; j < 8; j++)
#pragma unroll
            for (int k = 0; k < 4; k++) c[i][j][k] = 0.f;

    const __nv_bfloat16* APl[3] = {Ahi, Ahi, Alo};
    const __nv_bfloat16* BPl[3] = {Bhi, Blo, Bhi};

    // global staging: row = tid>>1 (0..127), segs s = 2*(tid&1)+{0,1} (8 bf16 each)
    const int grow = tid >> 1;
    const int gs0 = (tid & 1) * 2;

    // ldmatrix addresses (bf16 units -> bytes)
    const uint32_t sa0 = smem_u32(&sA[0][0]);
    const uint32_t sb0 = smem_u32(&sB[0][0]);
    const int arow = wm + (lane & 15);
    const int acolb = ((lane >> 4) << 3);
    // B ldmatrix i: row = wn + i*16 + ((lane>>4)<<3) + (lane&7), col = ((lane>>3)&1)*8
    const int brow_base = wn + ((lane >> 4) << 3) + (lane & 7);
    const int bcolb = ((lane >> 3) & 1) * 8;

    uint4 va[2], vb[2];
    // preload chunk 0 (prod 0: Ahi, Bhi)
    {
        const __nv_bfloat16* ap = APl[0];
        const __nv_bfloat16* bp = BPl[0];
#pragma unroll
        for (int j = 0; j < 2; j++) {
            const int s = gs0 + j;
            va[j] = *reinterpret_cast<const uint4*>(ap + (size_t)(m0 + grow) * 512 + s * 8);
            vb[j] = *reinterpret_cast<const uint4*>(bp + (size_t)(n0 + grow) * 512 + s * 8);
        }
#pragma unroll
        for (int j = 0; j < 2; j++) {
            const int s = gs0 + j;
            *reinterpret_cast<uint4*>(&sA[0][grow * SST + s * 8]) = va[j];
            *reinterpret_cast<uint4*>(&sB[0][grow * SST + s * 8]) = vb[j];
        }
    }
    __syncthreads();

    int buf = 0;
    for (int cc = 0; cc < 48; cc++) {
        // prefetch next chunk into regs
        if (cc + 1 < 48) {
            const int prod = (cc + 1) >> 4;
            const int kc = ((cc + 1) & 15) * 32;
            const __nv_bfloat16* ap = APl[prod];
            const __nv_bfloat16* bp = BPl[prod];
#pragma unroll
            for (int j = 0; j < 2; j++) {
                const int s = gs0 + j;
                va[j] = *reinterpret_cast<const uint4*>(
                    ap + (size_t)(m0 + grow) * 512 + kc + s * 8);
                vb[j] = *reinterpret_cast<const uint4*>(
                    bp + (size_t)(n0 + grow) * 512 + kc + s * 8);
            }
        }
        // compute from smem[buf]
        const uint32_t sab = sa0 + (uint32_t)buf * (128 * SST * 2);
        const uint32_t sbb = sb0 + (uint32_t)buf * (128 * SST * 2);
#pragma unroll
        for (int kf = 0; kf < 2; kf++) {
            uint32_t a[2][4], b[4][4];
#pragma unroll
            for (int mf = 0; mf < 2; mf++)
                ldm_x4(a[mf], sab + (uint32_t)(((arow + mf * 16) * SST + acolb + kf * 16) * 2));
#pragma unroll
            for (int i4 = 0; i4 < 4; i4++)
                ldm_x4(b[i4], sbb + (uint32_t)(((brow_base + i4 * 16) * SST + bcolb + kf * 16) * 2));
#pragma unroll
            for (int mf = 0; mf < 2; mf++)
#pragma unroll
                for (int i4 = 0; i4 < 4; i4++) {
                    mma_bf16(c[mf][i4 * 2 + 0], a[mf], &b[i4][0]);
                    mma_bf16(c[mf][i4 * 2 + 1], a[mf], &b[i4][2]);
                }
        }
        // store prefetched chunk to other buffer
        if (cc + 1 < 48) {
            const int nb = buf ^ 1;
#pragma unroll
            for (int j = 0; j < 2; j++) {
                const int s = gs0 + j;
                *reinterpret_cast<uint4*>(&sA[nb][grow * SST + s * 8]) = va[j];
                *reinterpret_cast<uint4*>(&sB[nb][grow * SST + s * 8]) = vb[j];
            }
            __syncthreads();
            buf = nb;
        }
    }

    // ---- epilogue ----
    float bv[8][2];
#pragma unroll
    for (int nf = 0; nf < 8; nf++) {
        const int col = n0 + wn + nf * 8 + (lane & 3) * 2;
        bv[nf][0] = __ldg(&bias[col]);
        bv[nf][1] = __ldg(&bias[col + 1]);
    }
    const int nact = g_nact;
#pragma unroll
    for (int mf = 0; mf < 2; mf++) {
#pragma unroll
        for (int half = 0; half < 2; half++) {
            const int rloc = wm + mf * 16 + (lane >> 2) + half * 8;
            const int r = m0 + rloc;
            float* dst;
            if (mode == 1) {
                if (r >= nact) continue;
                const int v = g_list[r];
                dst = outp + ((size_t)(v & 63) * T_ + (v >> 6)) * ldout;
            } else {
                dst = outp + (size_t)r * ldout;
            }
#pragma unroll
            for (int nf = 0; nf < 8; nf++) {
                const int col = n0 + wn + nf * 8 + (lane & 3) * 2;
                float2 o;
                o.x = c[mf][nf][half * 2 + 0] + bv[nf][0];
                o.y = c[mf][nf][half * 2 + 1] + bv[nf][1];
                *reinterpret_cast<float2*>(dst + col) = o;
            }
        }
    }
}

// ---------------- bf16 split conversion kernels ----------------
__global__ void conv_split_kernel(const float* __restrict__ X,
                                  __nv_bfloat16* __restrict__ hi,
                                  __nv_bfloat16* __restrict__ lo, int n)
{
    const int stride = gridDim.x * blockDim.x;
    for (int i = blockIdx.x * blockDim.x + threadIdx.x; i < n; i += stride) {
        const float x = X[i];
        const __nv_bfloat16 h = __float2bfloat16(x);
        hi[i] = h;
        lo[i] = __float2bfloat16(x - __bfloat162float(h));
    }
}

// EO [b][c][p] -> enc hi/lo [(b*256+p)][c]
__global__ void conv_enc_kernel(const float* __restrict__ EO)
{
    __shared__ float tile[32][33];
    const int b = blockIdx.z;
    const int c0 = blockIdx.y * 32;
    const int p0 = blockIdx.x * 32;
    const int tx = threadIdx.x, ty = threadIdx.y;
#pragma unroll
    for (int j = 0; j < 32; j += 8)
        tile[ty + j][tx] = EO[((size_t)b * ENC_ + (c0 + ty + j)) * P_ + p0 + tx];
    __syncthreads();
#pragma unroll
    for (int j = 0; j < 32; j += 8) {
        const float x = tile[tx][ty + j];
        const __nv_bfloat16 h = __float2bfloat16(x);
        const size_t idx = ((size_t)b * P_ + (p0 + ty + j)) * ENC_ + c0 + tx;
        g_enc_hi[idx] = h;
        g_enc_lo[idx] = __float2bfloat16(x - __bfloat162float(h));
    }
}

// gather active h rows -> padded bf16 hi/lo A for fc
__global__ void conv_fcA_kernel()
{
    const int r = blockIdx.x;
    const int nact = g_nact;
    if (r < nact) {
        const float* src = g_hall + (size_t)g_list[r] * DEC_;
        for (int k = threadIdx.x; k < DEC_; k += blockDim.x) {
            const float x = src[k];
            const __nv_bfloat16 h = __float2bfloat16(x);
            g_Afc_hi[(size_t)r * DEC_ + k] = h;
            g_Afc_lo[(size_t)r * DEC_ + k] = __float2bfloat16(x - __bfloat162float(h));
        }
    } else {
        const __nv_bfloat16 z = __float2bfloat16(0.f);
        for (int k = threadIdx.x; k < DEC_; k += blockDim.x) {
            g_Afc_hi[(size_t)r * DEC_ + k] = z;
            g_Afc_lo[(size_t)r * DEC_ + k] = z;
        }
    }
}

// ---------------- software grid barrier ----------------
__device__ __forceinline__ void grid_bar() {
    __syncthreads();
    if (threadIdx.x == 0) {
        __threadfence();
        unsigned gen = *((volatile unsigned*)&g_bar_gen);
        unsigned t = atomicAdd(&g_bar_count, 1u);
        if (t == NB_ - 1) {
            g_bar_count = 0;
            __threadfence();
            *((volatile unsigned*)&g_bar_gen) = gen + 1;
        } else {
            while (*((volatile unsigned*)&g_bar_gen) == gen) __nanosleep(64);
        }
    }
    __syncthreads();
}

// ================= persistent decode-loop kernel =================
__global__ __launch_bounds__(256, 1) void step_kernel(
    const float* __restrict__ EO, const float* __restrict__ emb,
    const int* __restrict__ caps, const float* __restrict__ wfull,
    const float* __restrict__ bfull)
{
    __shared__ __align__(16) float pool[4360];
    const int tid = threadIdx.x;
    const int lane = tid & 31, warp = tid >> 5;

    for (int t = 0; t < T_; t++) {
        // ---- Phase A: ab[64x1024] = h @ Wab^T + bab ----
        {
            float* Ws = pool;
            const int n0 = blockIdx.x * 8;
            for (int i = tid; i < 8 * 512; i += 256) {
                const int r = i >> 9, c = i & 511;
                Ws[r * 516 + c] = g_Wab[(size_t)(n0 + r) * 512 + c];
            }
            __syncthreads();
            const int b = tid >> 2;
            const int nl0 = (tid & 3) << 1;
            const float* hb = g_state + b * 1024;
            const float* w0p = Ws + nl0 * 516;
            const float* w1p = Ws + (nl0 + 1) * 516;
            float4 s0 = {0.f,0.f,0.f,0.f}, s1 = {0.f,0.f,0.f,0.f};
#pragma unroll 4
            for (int k = 0; k < 512; k += 4) {
                float4 hv = ldcg4(hb + k);
                float4 w0 = *reinterpret_cast<const float4*>(w0p + k);
                float4 w1 = *reinterpret_cast<const float4*>(w1p + k);
                s0.x = fmaf(hv.x, w0.x, s0.x); s0.y = fmaf(hv.y, w0.y, s0.y);
                s0.z = fmaf(hv.z, w0.z, s0.z); s0.w = fmaf(hv.w, w0.w, s0.w);
                s1.x = fmaf(hv.x, w1.x, s1.x); s1.y = fmaf(hv.y, w1.y, s1.y);
                s1.z = fmaf(hv.z, w1.z, s1.z); s1.w = fmaf(hv.w, w1.w, s1.w);
            }
            g_ab[b * 1024 + n0 + nl0]     = s0.x + s0.y + s0.z + s0.w + g_bab[n0 + nl0];
            g_ab[b * 1024 + n0 + nl0 + 1] = s1.x + s1.y + s1.z + s1.w + g_bab[n0 + nl0 + 1];
        }
        grid_bar();

        // ---- Phase B: attention + softmax + gated awe + xinh ----
        if (blockIdx.x < 64) {
            float* attb = pool;
            float* ws   = pool + 1024;
            float* es   = pool + 1536;
            float* red  = pool + 1792;
            float* sv   = pool + 1800;
            const int b = blockIdx.x;

            for (int a = tid; a < 1024; a += 256) attb[a] = __ldcg(&g_ab[b * 1024 + a]);
            ws[tid] = wfull[tid];
            ws[tid + 256] = wfull[tid + 256];
            __syncthreads();

            const float bf = bfull[0];
            for (int p = warp; p < P_; p += 8) {
                const float* arow = g_att1 + ((size_t)b * P_ + p) * ATT_;
                float s = 0.f;
                for (int a = lane; a < ATT_; a += 32) {
                    float v = arow[a] + attb[a];
                    v = fmaxf(v, 0.f);
                    s = fmaf(v, ws[a], s);
                }
#pragma unroll
                for (int o = 16; o; o >>= 1) s += __shfl_xor_sync(0xffffffffu, s, o);
                if (!lane) es[p] = s + bf;
            }
            __syncthreads();

            float v = es[tid];
            float mx = v;
#pragma unroll
            for (int o = 16; o; o >>= 1) mx = fmaxf(mx, __shfl_xor_sync(0xffffffffu, mx, o));
            if (!lane) red[warp] = mx;
            __syncthreads();
            if (tid == 0) {
                float mm = red[0];
#pragma unroll
                for (int i = 1; i < 8; i++) mm = fmaxf(mm, red[i]);
                sv[0] = mm;
            }
            __syncthreads();
            float ex = __expf(v - sv[0]);
            float s2 = ex;
#pragma unroll
            for (int o = 16; o; o >>= 1) s2 += __shfl_xor_sync(0xffffffffu, s2, o);
            if (!lane) red[warp] = s2;
            __syncthreads();
            if (tid == 0) {
                float ss = 0.f;
#pragma unroll
                for (int i = 0; i < 8; i++) ss += red[i];
                sv[0] = ss;
            }
            __syncthreads();
            es[tid] = ex / sv[0];
            __syncthreads();

            for (int c = warp; c < ENC_; c += 8) {
                const float* eop = EO + ((size_t)b * ENC_ + c) * P_;
                float s = 0.f;
                for (int p = lane; p < P_; p += 32) s = fmaf(es[p], eop[p], s);
#pragma unroll
                for (int o = 16; o; o >>= 1) s += __shfl_xor_sync(0xffffffffu, s, o);
                if (!lane) {
                    float gate = 1.f / (1.f + __expf(-attb[512 + c]));
                    g_xinh[b * 1280 + 256 + c] = gate * s;
                }
            }
            const int tok = caps[b * L_ + t];
            g_xinh[b * 1280 + tid] = emb[(size_t)tok * EMB_ + tid];
            g_xinh[b * 1280 + 768 + tid]       = __ldcg(&g_state[b * 1024 + tid]);
            g_xinh[b * 1280 + 768 + 256 + tid] = __ldcg(&g_state[b * 1024 + 256 + tid]);
        }
        grid_bar();

        // ---- Phase C: gates split-K GEMM ----
        {
            float (*As2)[16][68] = reinterpret_cast<float(*)[16][68]>(pool);
            float (*Ws2)[16][68] = reinterpret_cast<float(*)[16][68]>(pool + 2176);
            const int jn = blockIdx.x & 31, jk = blockIdx.x >> 5;
            const int n0 = jn * 64, k0 = jk * 320;
            const int lr = tid >> 2, lk = (tid & 3) << 2;
            const int tx = tid & 15, ty = tid >> 4;
            const float* aP = g_xinh + lr * 1280 + k0 + lk;
            const float* wP = g_Wlstm + (size_t)(n0 + lr) * 1280 + k0 + lk;

            float acc[4][4];
#pragma unroll
            for (int i = 0; i < 4; i++)
#pragma unroll
                for (int j = 0; j < 4; j++) acc[i][j] = 0.f;

            float4 a = ldcg4(aP);
            float4 w = *reinterpret_cast<const float4*>(wP);
            {
                float ar[4] = {a.x, a.y, a.z, a.w};
                float wr[4] = {w.x, w.y, w.z, w.w};
#pragma unroll
                for (int j = 0; j < 4; j++) {
                    As2[0][lk + j][lr] = ar[j];
                    Ws2[0][lk + j][lr] = wr[j];
                }
            }
            __syncthreads();
            int buf = 0;
            for (int s = 0; s < 20; s++) {
                if (s + 1 < 20) {
                    a = ldcg4(aP + (s + 1) * 16);
                    w = *reinterpret_cast<const float4*>(wP + (s + 1) * 16);
                }
#pragma unroll
                for (int kk = 0; kk < 16; kk++) {
                    float4 av = *reinterpret_cast<const float4*>(&As2[buf][kk][ty << 2]);
                    float4 wv = *reinterpret_cast<const float4*>(&Ws2[buf][kk][tx << 2]);
                    float ar[4] = {av.x, av.y, av.z, av.w};
                    float wr[4] = {wv.x, wv.y, wv.z, wv.w};
#pragma unroll
                    for (int i = 0; i < 4; i++)
#pragma unroll
                        for (int j = 0; j < 4; j++)
                            acc[i][j] = fmaf(ar[i], wr[j], acc[i][j]);
                }
                if (s + 1 < 20) {
                    int nb = buf ^ 1;
                    float ar[4] = {a.x, a.y, a.z, a.w};
                    float wr[4] = {w.x, w.y, w.z, w.w};
#pragma unroll
                    for (int j = 0; j < 4; j++) {
                        As2[nb][lk + j][lr] = ar[j];
                        Ws2[nb][lk + j][lr] = wr[j];
                    }
                    __syncthreads();
                    buf = nb;
                }
            }
            float* cp = g_gp + (size_t)jk * (B_ * 2048);
#pragma unroll
            for (int i = 0; i < 4; i++) {
                float4 o;
                o.x = acc[i][0]; o.y = acc[i][1]; o.z = acc[i][2]; o.w = acc[i][3];
                *reinterpret_cast<float4*>(cp + (size_t)((ty << 2) + i) * 2048 + n0 + (tx << 2)) = o;
            }
        }
        grid_bar();

        // ---- Phase D: LSTM cell ----
        if (blockIdx.x < 64) {
            const int b = blockIdx.x;
            for (int dd = tid; dd < 512; dd += 256) {
                float gi = g_blstm[dd];
                float gf = g_blstm[512 + dd];
                float gg = g_blstm[1024 + dd];
                float go = g_blstm[1536 + dd];
#pragma unroll
                for (int s = 0; s < GKS_; s++) {
                    const float* base = g_gp + (size_t)s * (B_ * 2048) + b * 2048;
                    gi += __ldcg(base + dd);
                    gf += __ldcg(base + 512 + dd);
                    gg += __ldcg(base + 1024 + dd);
                    go += __ldcg(base + 1536 + dd);
                }
                const float c = __ldcg(&g_state[b * 1024 + 512 + dd]);
                const float si = 1.f / (1.f + __expf(-gi));
                const float sf = 1.f / (1.f + __expf(-gf));
                const float so = 1.f / (1.f + __expf(-go));
                const float c2 = sf * c + si * tanhf(gg);
                const float h2 = so * tanhf(c2);
                g_state[b * 1024 + dd] = h2;
                g_state[b * 1024 + 512 + dd] = c2;
                g_hall[((size_t)t * B_ + b) * DEC_ + dd] = h2;
            }
        }
        grid_bar();
    }
}

// ============ 64x64 GEMM with bias (h0/c0 init only) =============
__global__ __launch_bounds__(256) void gemm64_kernel(
    const float* __restrict__ A, int lda,
    const float* __restrict__ W, int ldw,
    const float* __restrict__ bias,
    float* __restrict__ C, int ldc, int K)
{
    __shared__ __align__(16) float As[16][64];
    __shared__ __align__(16) float Ws[16][64];
    const int tid = threadIdx.x;
    const int m0 = blockIdx.y * 64;
    const int n0 = blockIdx.x * 64;
    const int lr = tid >> 2;
    const int lk = (tid & 3) << 2;
    const int tx = tid & 15;
    const int ty = tid >> 4;

    float acc[4][4];
#pragma unroll
    for (int i = 0; i < 4; i++)
#pragma unroll
        for (int j = 0; j < 4; j++) acc[i][j] = 0.f;

    const float* aptr = A + (size_t)(m0 + lr) * lda + lk;
    const float* wptr = W + (size_t)(n0 + lr) * ldw + lk;

    for (int k0 = 0; k0 < K; k0 += 16) {
        float4 av = *reinterpret_cast<const float4*>(aptr + k0);
        float4 wv = *reinterpret_cast<const float4*>(wptr + k0);
        As[lk + 0][lr] = av.x; As[lk + 1][lr] = av.y;
        As[lk + 2][lr] = av.z; As[lk + 3][lr] = av.w;
        Ws[lk + 0][lr] = wv.x; Ws[lk + 1][lr] = wv.y;
        Ws[lk + 2][lr] = wv.z; Ws[lk + 3][lr] = wv.w;
        __syncthreads();
#pragma unroll
        for (int kk = 0; kk < 16; kk++) {
            float4 a = *reinterpret_cast<const float4*>(&As[kk][ty << 2]);
            float4 b = *reinterpret_cast<const float4*>(&Ws[kk][tx << 2]);
            float ar[4] = {a.x, a.y, a.z, a.w};
            float br[4] = {b.x, b.y, b.z, b.w};
#pragma unroll
            for (int i = 0; i < 4; i++)
#pragma unroll
                for (int j = 0; j < 4; j++)
                    acc[i][j] = fmaf(ar[i], br[j], acc[i][j]);
        }
        __syncthreads();
    }
    const int n = n0 + (tx << 2);
#pragma unroll
    for (int i = 0; i < 4; i++) {
        const int m = m0 + (ty << 2) + i;
        float4 outv;
        outv.x = acc[i][0] + bias[n + 0];
        outv.y = acc[i][1] + bias[n + 1];
        outv.z = acc[i][2] + bias[n + 2];
        outv.w = acc[i][3] + bias[n + 3];
        *reinterpret_cast<float4*>(&C[(size_t)m * ldc + n]) = outv;
    }
}

// ---------------- prep kernels ----------------
__global__ void prep_weights_kernel(
    const float* __restrict__ Wdec, const float* __restrict__ bdec,
    const float* __restrict__ Wbeta, const float* __restrict__ bbeta,
    const float* __restrict__ Wih, const float* __restrict__ Whh,
    const float* __restrict__ bih, const float* __restrict__ bhh,
    const float* __restrict__ Winith, const float* __restrict__ binith,
    const float* __restrict__ Winitc, const float* __restrict__ binitc)
{
    const int stride = gridDim.x * blockDim.x;
    const int i0 = blockIdx.x * blockDim.x + threadIdx.x;
    for (int i = i0; i < 512 * 512; i += stride) {
        g_Wab[i] = Wdec[i];
        g_Wab[512 * 512 + i] = Wbeta[i];
        g_Winit[i] = Winith[i];
        g_Winit[512 * 512 + i] = Winitc[i];
    }
    for (int i = i0; i < 512; i += stride) {
        g_bab[i] = bdec[i];       g_bab[512 + i] = bbeta[i];
        g_binit[i] = binith[i];   g_binit[512 + i] = binitc[i];
    }
    for (int i = i0; i < 2048 * 1280; i += stride) {
        int nrow = i / 1280, k = i - nrow * 1280;
        g_Wlstm[i] = (k < 768) ? Wih[nrow * 768 + k] : Whh[nrow * 512 + (k - 768)];
    }
    for (int i = i0; i < 2048; i += stride) g_blstm[i] = bih[i] + bhh[i];
}

__global__ void build_list_kernel(const int* __restrict__ lens)
{
    __shared__ int offs[64];
    const int b = threadIdx.x;
    if (b == 0) {
        int o = 0;
        for (int i = 0; i < B_; i++) { offs[i] = o; o += lens[i] - 1; }
        g_nact = o;
    }
    __syncthreads();
    if (b < B_) {
        const int o = offs[b];
        const int n = lens[b] - 1;
        for (int t = 0; t < n; t++) g_list[o + t] = (t << 6) | b;
    }
}

__global__ void zerofill_kernel(const int* __restrict__ lens, float* __restrict__ out)
{
    const int b = blockIdx.x / T_;
    const int t = blockIdx.x % T_;
    if (t < lens[b] - 1) return;
    float4 z; z.x = z.y = z.z = z.w = 0.f;
    float4* o = reinterpret_cast<float4*>(out + ((size_t)b * T_ + t) * V_);
    for (int i = threadIdx.x; i < V_ / 4; i += blockDim.x) o[i] = z;
}

__global__ void meanenc_kernel(const float* __restrict__ EO)
{
    const int wg = (blockIdx.x * blockDim.x + threadIdx.x) >> 5;
    const int lane = threadIdx.x & 31;
    if (wg >= B_ * ENC_) return;
    const float* row = EO + (size_t)wg * P_;
    float s = 0.f;
    for (int p = lane; p < P_; p += 32) s += row[p];
#pragma unroll
    for (int o = 16; o; o >>= 1) s += __shfl_xor_sync(0xffffffffu, s, o);
    if (!lane) g_meanenc[wg] = s * (1.0f / P_);
}

// ---------------- launch ----------------
extern "C" void kernel_launch(void* const* d_in, const int* in_sizes, int n_in,
                              void* d_out, int out_size)
{
    const float* EO        = (const float*)d_in[0];
    const int*   caps      = (const int*)  d_in[1];
    const int*   lens      = (const int*)  d_in[2];
    const float* W_enc_att = (const float*)d_in[3];
    const float* b_enc_att = (const float*)d_in[4];
    const float* W_dec_att = (const float*)d_in[5];
    const float* b_dec_att = (const float*)d_in[6];
    const float* w_full    = (const float*)d_in[7];
    const float* b_full    = (const float*)d_in[8];
    const float* emb       = (const float*)d_in[9];
    const float* W_ih      = (const float*)d_in[10];
    const float* W_hh      = (const float*)d_in[11];
    const float* b_ih      = (const float*)d_in[12];
    const float* b_hh      = (const float*)d_in[13];
    const float* W_init_h  = (const float*)d_in[14];
    const float* b_init_h  = (const float*)d_in[15];
    const float* W_init_c  = (const float*)d_in[16];
    const float* b_init_c  = (const float*)d_in[17];
    const float* W_beta    = (const float*)d_in[18];
    const float* b_beta    = (const float*)d_in[19];
    const float* W_fc      = (const float*)d_in[20];
    const float* b_fc      = (const float*)d_in[21];
    float* out = (float*)d_out;

    float *state, *meanenc, *Winit, *binit, *att1;
    __nv_bfloat16 *ench, *encl, *wench, *wencl, *wfch, *wfcl, *afch, *afcl;
    cudaGetSymbolAddress((void**)&state,   g_state);
    cudaGetSymbolAddress((void**)&meanenc, g_meanenc);
    cudaGetSymbolAddress((void**)&Winit,   g_Winit);
    cudaGetSymbolAddress((void**)&binit,   g_binit);
    cudaGetSymbolAddress((void**)&att1,    g_att1);
    cudaGetSymbolAddress((void**)&ench,    g_enc_hi);
    cudaGetSymbolAddress((void**)&encl,    g_enc_lo);
    cudaGetSymbolAddress((void**)&wench,   g_Wenc_hi);
    cudaGetSymbolAddress((void**)&wencl,   g_Wenc_lo);
    cudaGetSymbolAddress((void**)&wfch,    g_Wfc_hi);
    cudaGetSymbolAddress((void**)&wfcl,    g_Wfc_lo);
    cudaGetSymbolAddress((void**)&afch,    g_Afc_hi);
    cudaGetSymbolAddress((void**)&afcl,    g_Afc_lo);

    // ---- one-time prep ----
    prep_weights_kernel<<<512, 256>>>(W_dec_att, b_dec_att, W_beta, b_beta,
                                      W_ih, W_hh, b_ih, b_hh,
                                      W_init_h, b_init_h, W_init_c, b_init_c);
    build_list_kernel<<<1, 64>>>(lens);
    zerofill_kernel<<<B_ * T_, 256>>>(lens, out);
    meanenc_kernel<<<4096, 256>>>(EO);
    gemm64_kernel<<<dim3(16, 1), 256>>>(meanenc, 512, Winit, 512, binit,
                                        state, 1024, 512);

    // bf16 conversions for tensor-core GEMMs
    conv_split_kernel<<<512, 256>>>(W_enc_att, wench, wencl, ATT_ * ENC_);
    conv_enc_kernel<<<dim3(8, 16, 64), dim3(32, 8)>>>(EO);
    conv_split_kernel<<<4096, 256>>>(W_fc, wfch, wfcl, V_ * DEC_);

    // att1 = enc @ W_enc_att^T + b  via HMMA (grid: 4 n-tiles x 128 m-tiles)
    mma_gemm_kernel<<<dim3(4, 128), 256>>>(ench, encl, wench, wencl,
                                           b_enc_att, att1, ATT_, 0);

    // ---- full decode recurrence in ONE persistent kernel ----
    step_kernel<<<NB_, 256>>>(EO, emb, caps, w_full, b_full);

    // ---- fc on gathered active rows via HMMA ----
    conv_fcA_kernel<<<MROWS_FC, 256>>>();
    mma_gemm_kernel<<<dim3(125, 16), 256>>>(afch, afcl, wfch, wfcl,
                                            b_fc, out, V_, 1);
}

// round 12
// speedup vs baseline: 1.3397x; 1.3397x over previous
#include <cuda_runtime.h>
#include <cuda_bf16.h>
#include <cstdint>

#define B_   64
#define L_   32
#define T_   31
#define V_   16000
#define ENC_ 512
#define DEC_ 512
#define ATT_ 512
#define EMB_ 256
#define P_   256

#define NB_    128
#define MROWS_FC 2048

// step_kernel dynamic smem layout (floats)
#define SW_STRIDE 1284
#define OFF_SW    0                       // 16 x 1284 = 20544
#define OFF_SWAB  20544                   // 8 x 516   = 4128
#define OFF_WS    24672                   // 512
#define OFF_SCR   25184                   // 4608 scratch (A-tiles / attb+es / gates)
#define STEP_SMEM ((25184 + 4608) * 4)    // 119168 bytes

// ---------------- device scratch ----------------
__device__ float g_state[B_ * 1024];
__device__ float g_meanenc[B_ * ENC_];
__device__ float g_att1[B_ * P_ * ATT_];
__device__ float g_Wab[1024 * 512];
__device__ float g_bab[1024];
__device__ float g_Winit[1024 * 512];
__device__ float g_binit[1024];
__device__ float g_Wlstm[2048 * 1280];    // row n' = 4*d + gate
__device__ float g_blstm[2048];
__device__ float g_ab[B_ * 1024];
__device__ float g_xinh[B_ * 1280];
__device__ float g_hall[T_ * B_ * DEC_];
__device__ int   g_list[T_ * B_];
__device__ int   g_nact;
__device__ int   g_cnt[T_];
__device__ unsigned g_bar_count = 0;
__device__ unsigned g_bar_gen   = 0;

// bf16 hi/lo planes
__device__ __nv_bfloat16 g_enc_hi[B_ * P_ * ENC_];
__device__ __nv_bfloat16 g_enc_lo[B_ * P_ * ENC_];
__device__ __nv_bfloat16 g_Wenc_hi[ATT_ * ENC_];
__device__ __nv_bfloat16 g_Wenc_lo[ATT_ * ENC_];
__device__ __nv_bfloat16 g_Wfc_hi[V_ * DEC_];
__device__ __nv_bfloat16 g_Wfc_lo[V_ * DEC_];
__device__ __nv_bfloat16 g_Afc_hi[MROWS_FC * DEC_];
__device__ __nv_bfloat16 g_Afc_lo[MROWS_FC * DEC_];

__device__ __forceinline__ float4 ldcg4(const float* p) {
    return __ldcg(reinterpret_cast<const float4*>(p));
}
__device__ __forceinline__ uint32_t smem_u32(const void* p) {
    uint32_t a;
    asm("{ .reg .u64 t; cvta.to.shared.u64 t, %1; cvt.u32.u64 %0, t; }"
        : "=r"(a) : "l"(p));
    return a;
}
__device__ __forceinline__ void ldm_x4(uint32_t* r, uint32_t addr) {
    asm volatile("ldmatrix.sync.aligned.m8n8.x4.shared.b16 {%0,%1,%2,%3}, [%4];"
                 : "=r"(r[0]), "=r"(r[1]), "=r"(r[2]), "=r"(r[3]) : "r"(addr));
}
__device__ __forceinline__ void mma_bf16(float* c, const uint32_t* a, const uint32_t* b) {
    asm volatile(
        "mma.sync.aligned.m16n8k16.row.col.f32.bf16.bf16.f32 "
        "{%0,%1,%2,%3}, {%4,%5,%6,%7}, {%8,%9}, {%0,%1,%2,%3};"
        : "+f"(c[0]), "+f"(c[1]), "+f"(c[2]), "+f"(c[3])
        : "r"(a[0]), "r"(a[1]), "r"(a[2]), "r"(a[3]), "r"(b[0]), "r"(b[1]));
}

// ============ HMMA bf16-split GEMM (unchanged from passing R5) ============
#define SST 40
__global__ __launch_bounds__(256) void mma_gemm_kernel(
    const __nv_bfloat16* __restrict__ Ahi, const __nv_bfloat16* __restrict__ Alo,
    const __nv_bfloat16* __restrict__ Bhi, const __nv_bfloat16* __restrict__ Blo,
    const float* __restrict__ bias, float* __restrict__ outp,
    int ldout, int mode)
{
    const int m0 = blockIdx.y * 128;
    const int n0 = blockIdx.x * 128;
    if (mode == 1 && m0 >= g_nact) return;

    __shared__ __align__(16) __nv_bfloat16 sA[2][128 * SST];
    __shared__ __align__(16) __nv_bfloat16 sB[2][128 * SST];

    const int tid = threadIdx.x;
    const int lane = tid & 31, wid = tid >> 5;
    const int wm = (wid & 3) * 32;
    const int wn = (wid >> 2) * 64;

    float c[2][8][4];
#pragma unroll
    for (int i = 0; i < 2; i++)
#pragma unroll
        for (int j = 0; j < 8; j++)
#pragma unroll
            for (int k = 0; k < 4; k++) c[i][j][k] = 0.f;

    const __nv_bfloat16* APl[3] = {Ahi, Ahi, Alo};
    const __nv_bfloat16* BPl[3] = {Bhi, Blo, Bhi};

    const int grow = tid >> 1;
    const int gs0 = (tid & 1) * 2;

    const uint32_t sa0 = smem_u32(&sA[0][0]);
    const uint32_t sb0 = smem_u32(&sB[0][0]);
    const int arow = wm + (lane & 15);
    const int acolb = ((lane >> 4) << 3);
    const int brow_base = wn + ((lane >> 4) << 3) + (lane & 7);
    const int bcolb = ((lane >> 3) & 1) * 8;

    uint4 va[2], vb[2];
    {
        const __nv_bfloat16* ap = APl[0];
        const __nv_bfloat16* bp = BPl[0];
#pragma unroll
        for (int j = 0; j < 2; j++) {
            const int s = gs0 + j;
            va[j] = *reinterpret_cast<const uint4*>(ap + (size_t)(m0 + grow) * 512 + s * 8);
            vb[j] = *reinterpret_cast<const uint4*>(bp + (size_t)(n0 + grow) * 512 + s * 8);
        }
#pragma unroll
        for (int j = 0; j < 2; j++) {
            const int s = gs0 + j;
            *reinterpret_cast<uint4*>(&sA[0][grow * SST + s * 8]) = va[j];
            *reinterpret_cast<uint4*>(&sB[0][grow * SST + s * 8]) = vb[j];
        }
    }
    __syncthreads();

    int buf = 0;
    for (int cc = 0; cc < 48; cc++) {
        if (cc + 1 < 48) {
            const int prod = (cc + 1) >> 4;
            const int kc = ((cc + 1) & 15) * 32;
            const __nv_bfloat16* ap = APl[prod];
            const __nv_bfloat16* bp = BPl[prod];
#pragma unroll
            for (int j = 0; j < 2; j++) {
                const int s = gs0 + j;
                va[j] = *reinterpret_cast<const uint4*>(
                    ap + (size_t)(m0 + grow) * 512 + kc + s * 8);
                vb[j] = *reinterpret_cast<const uint4*>(
                    bp + (size_t)(n0 + grow) * 512 + kc + s * 8);
            }
        }
        const uint32_t sab = sa0 + (uint32_t)buf * (128 * SST * 2);
        const uint32_t sbb = sb0 + (uint32_t)buf * (128 * SST * 2);
#pragma unroll
        for (int kf = 0; kf < 2; kf++) {
            uint32_t a[2][4], b[4][4];
#pragma unroll
            for (int mf = 0; mf < 2; mf++)
                ldm_x4(a[mf], sab + (uint32_t)(((arow + mf * 16) * SST + acolb + kf * 16) * 2));
#pragma unroll
            for (int i4 = 0; i4 < 4; i4++)
                ldm_x4(b[i4], sbb + (uint32_t)(((brow_base + i4 * 16) * SST + bcolb + kf * 16) * 2));
#pragma unroll
            for (int mf = 0; mf < 2; mf++)
#pragma unroll
                for (int i4 = 0; i4 < 4; i4++) {
                    mma_bf16(c[mf][i4 * 2 + 0], a[mf], &b[i4][0]);
                    mma_bf16(c[mf][i4 * 2 + 1], a[mf], &b[i4][2]);
                }
        }
        if (cc + 1 < 48) {
            const int nb = buf ^ 1;
#pragma unroll
            for (int j = 0; j < 2; j++) {
                const int s = gs0 + j;
                *reinterpret_cast<uint4*>(&sA[nb][grow * SST + s * 8]) = va[j];
                *reinterpret_cast<uint4*>(&sB[nb][grow * SST + s * 8]) = vb[j];
            }
            __syncthreads();
            buf = nb;
        }
    }

    float bv[8][2];
#pragma unroll
    for (int nf = 0; nf < 8; nf++) {
        const int col = n0 + wn + nf * 8 + (lane & 3) * 2;
        bv[nf][0] = __ldg(&bias[col]);
        bv[nf][1] = __ldg(&bias[col + 1]);
    }
    const int nact = g_nact;
#pragma unroll
    for (int mf = 0; mf < 2; mf++) {
#pragma unroll
        for (int half = 0; half < 2; half++) {
            const int rloc = wm + mf * 16 + (lane >> 2) + half * 8;
            const int r = m0 + rloc;
            float* dst;
            if (mode == 1) {
                if (r >= nact) continue;
                const int v = g_list[r];
                dst = outp + ((size_t)(v & 63) * T_ + (v >> 6)) * ldout;
            } else {
                dst = outp + (size_t)r * ldout;
            }
#pragma unroll
            for (int nf = 0; nf < 8; nf++) {
                const int col = n0 + wn + nf * 8 + (lane & 3) * 2;
                float2 o;
                o.x = c[mf][nf][half * 2 + 0] + bv[nf][0];
                o.y = c[mf][nf][half * 2 + 1] + bv[nf][1];
                *reinterpret_cast<float2*>(dst + col) = o;
            }
        }
    }
}

// ---------------- bf16 split conversion kernels ----------------
__global__ void conv_split_kernel(const float* __restrict__ X,
                                  __nv_bfloat16* __restrict__ hi,
                                  __nv_bfloat16* __restrict__ lo, int n)
{
    const int stride = gridDim.x * blockDim.x;
    for (int i = blockIdx.x * blockDim.x + threadIdx.x; i < n; i += stride) {
        const float x = X[i];
        const __nv_bfloat16 h = __float2bfloat16(x);
        hi[i] = h;
        lo[i] = __float2bfloat16(x - __bfloat162float(h));
    }
}

__global__ void conv_enc_kernel(const float* __restrict__ EO)
{
    __shared__ float tile[32][33];
    const int b = blockIdx.z;
    const int c0 = blockIdx.y * 32;
    const int p0 = blockIdx.x * 32;
    const int tx = threadIdx.x, ty = threadIdx.y;
#pragma unroll
    for (int j = 0; j < 32; j += 8)
        tile[ty + j][tx] = EO[((size_t)b * ENC_ + (c0 + ty + j)) * P_ + p0 + tx];
    __syncthreads();
#pragma unroll
    for (int j = 0; j < 32; j += 8) {
        const float x = tile[tx][ty + j];
        const __nv_bfloat16 h = __float2bfloat16(x);
        const size_t idx = ((size_t)b * P_ + (p0 + ty + j)) * ENC_ + c0 + tx;
        g_enc_hi[idx] = h;
        g_enc_lo[idx] = __float2bfloat16(x - __bfloat162float(h));
    }
}

__global__ void conv_fcA_kernel()
{
    const int r = blockIdx.x;
    const int nact = g_nact;
    if (r < nact) {
        const float* src = g_hall + (size_t)g_list[r] * DEC_;
        for (int k = threadIdx.x; k < DEC_; k += blockDim.x) {
            const float x = src[k];
            const __nv_bfloat16 h = __float2bfloat16(x);
            g_Afc_hi[(size_t)r * DEC_ + k] = h;
            g_Afc_lo[(size_t)r * DEC_ + k] = __float2bfloat16(x - __bfloat162float(h));
        }
    } else {
        const __nv_bfloat16 z = __float2bfloat16(0.f);
        for (int k = threadIdx.x; k < DEC_; k += blockDim.x) {
            g_Afc_hi[(size_t)r * DEC_ + k] = z;
            g_Afc_lo[(size_t)r * DEC_ + k] = z;
        }
    }
}

// ---------------- software grid barrier ----------------
__device__ __forceinline__ void grid_bar() {
    __syncthreads();
    if (threadIdx.x == 0) {
        __threadfence();
        unsigned gen = *((volatile unsigned*)&g_bar_gen);
        unsigned t = atomicAdd(&g_bar_count, 1u);
        if (t == NB_ - 1) {
            g_bar_count = 0;
            __threadfence();
            *((volatile unsigned*)&g_bar_gen) = gen + 1;
        } else {
            while (*((volatile unsigned*)&g_bar_gen) == gen) __nanosleep(64);
        }
    }
    __syncthreads();
}

// ================= persistent decode-loop kernel (restructured) =================
// Phase A (128 blocks): ab = h @ Wab^T + bab (weights smem-resident)
// Phase B (cnt blocks): attention + softmax + gated awe -> xinh     (float4)
// Phase C (128 blocks): gates full-K GEMM (W' smem-resident) + LSTM cell fused
__global__ __launch_bounds__(256, 1) void step_kernel(
    const float* __restrict__ EO, const float* __restrict__ emb,
    const int* __restrict__ caps, const float* __restrict__ wfull,
    const float* __restrict__ bfull)
{
    extern __shared__ float dsm[];
    float* sW   = dsm + OFF_SW;     // [16][1284] gates weights (persistent)
    float* sWab = dsm + OFF_SWAB;   // [8][516]   att2|beta weights (persistent)
    float* ws   = dsm + OFF_WS;     // [512]      w_full (persistent)
    float* scr  = dsm + OFF_SCR;    // 4608 scratch

    const int tid = threadIdx.x;
    const int lane = tid & 31, warp = tid >> 5;
    const int j = blockIdx.x;

    // ---- one-time staging (weights constant across steps) ----
#pragma unroll
    for (int r = 0; r < 16; r++)
        for (int k = tid * 4; k < 1280; k += 1024)
            *reinterpret_cast<float4*>(&sW[r * SW_STRIDE + k]) =
                *reinterpret_cast<const float4*>(&g_Wlstm[(size_t)(j * 16 + r) * 1280 + k]);
    for (int i = tid; i < 8 * 512; i += 256) {
        const int r = i >> 9, c = i & 511;
        sWab[r * 516 + c] = g_Wab[(size_t)(j * 8 + r) * 512 + c];
    }
    ws[tid] = wfull[tid];
    ws[tid + 256] = wfull[tid + 256];
    __syncthreads();

    for (int t = 0; t < T_; t++) {
        const int cnt = __ldg(&g_cnt[t]);    // active rows: b < cnt

        // ---- Phase A ----
        {
            const int b = tid >> 2;
            if (b < cnt) {
                const int nl0 = (tid & 3) << 1;
                const float* hb = g_state + b * 1024;
                const float* w0p = sWab + nl0 * 516;
                const float* w1p = sWab + (nl0 + 1) * 516;
                float4 s0 = {0.f,0.f,0.f,0.f}, s1 = {0.f,0.f,0.f,0.f};
#pragma unroll 4
                for (int k = 0; k < 512; k += 4) {
                    float4 hv = ldcg4(hb + k);
                    float4 w0 = *reinterpret_cast<const float4*>(w0p + k);
                    float4 w1 = *reinterpret_cast<const float4*>(w1p + k);
                    s0.x = fmaf(hv.x, w0.x, s0.x); s0.y = fmaf(hv.y, w0.y, s0.y);
                    s0.z = fmaf(hv.z, w0.z, s0.z); s0.w = fmaf(hv.w, w0.w, s0.w);
                    s1.x = fmaf(hv.x, w1.x, s1.x); s1.y = fmaf(hv.y, w1.y, s1.y);
                    s1.z = fmaf(hv.z, w1.z, s1.z); s1.w = fmaf(hv.w, w1.w, s1.w);
                }
                const int n0 = j * 8;
                g_ab[b * 1024 + n0 + nl0]     = s0.x + s0.y + s0.z + s0.w + g_bab[n0 + nl0];
                g_ab[b * 1024 + n0 + nl0 + 1] = s1.x + s1.y + s1.z + s1.w + g_bab[n0 + nl0 + 1];
            }
        }
        grid_bar();

        // ---- Phase B ----
        if (j < cnt) {
            const int b = j;
            float* attb = scr;               // 1024
            float* es   = scr + 1024;        // 256
            float* red  = scr + 1280;        // 8
            float* sv   = scr + 1288;        // 1
            float4* attb4 = reinterpret_cast<float4*>(attb);
            float4* es4   = reinterpret_cast<float4*>(es);
            float4* ws4   = reinterpret_cast<float4*>(ws);

            attb4[tid] = ldcg4(&g_ab[b * 1024 + tid * 4]);
            __syncthreads();

            const float bf = bfull[0];
            for (int p = warp; p < 256; p += 8) {
                const float4* arow = reinterpret_cast<const float4*>(
                    g_att1 + ((size_t)b * 256 + p) * 512);
                float s = 0.f;
#pragma unroll
                for (int i = 0; i < 4; i++) {
                    float4 v  = __ldg(&arow[lane + i * 32]);
                    float4 a2 = attb4[lane + i * 32];
                    float4 wv = ws4[lane + i * 32];
                    s = fmaf(fmaxf(v.x + a2.x, 0.f), wv.x, s);
                    s = fmaf(fmaxf(v.y + a2.y, 0.f), wv.y, s);
                    s = fmaf(fmaxf(v.z + a2.z, 0.f), wv.z, s);
                    s = fmaf(fmaxf(v.w + a2.w, 0.f), wv.w, s);
                }
#pragma unroll
                for (int o = 16; o; o >>= 1) s += __shfl_xor_sync(0xffffffffu, s, o);
                if (!lane) es[p] = s + bf;
            }
            __syncthreads();

            float v = es[tid];
            float mx = v;
#pragma unroll
            for (int o = 16; o; o >>= 1) mx = fmaxf(mx, __shfl_xor_sync(0xffffffffu, mx, o));
            if (!lane) red[warp] = mx;
            __syncthreads();
            if (tid == 0) {
                float mm = red[0];
#pragma unroll
                for (int i = 1; i < 8; i++) mm = fmaxf(mm, red[i]);
                sv[0] = mm;
            }
            __syncthreads();
            float ex = __expf(v - sv[0]);
            float s2 = ex;
#pragma unroll
            for (int o = 16; o; o >>= 1) s2 += __shfl_xor_sync(0xffffffffu, s2, o);
            if (!lane) red[warp] = s2;
            __syncthreads();
            if (tid == 0) {
                float ss = 0.f;
#pragma unroll
                for (int i = 0; i < 8; i++) ss += red[i];
                sv[0] = ss;
            }
            __syncthreads();
            es[tid] = ex / sv[0];
            __syncthreads();

            for (int c = warp; c < 512; c += 8) {
                const float4* eop = reinterpret_cast<const float4*>(
                    EO + ((size_t)b * 512 + c) * 256);
                float s = 0.f;
#pragma unroll
                for (int i = 0; i < 2; i++) {
                    float4 al = es4[lane + i * 32];
                    float4 e  = __ldg(&eop[lane + i * 32]);
                    s = fmaf(al.x, e.x, s); s = fmaf(al.y, e.y, s);
                    s = fmaf(al.z, e.z, s); s = fmaf(al.w, e.w, s);
                }
#pragma unroll
                for (int o = 16; o; o >>= 1) s += __shfl_xor_sync(0xffffffffu, s, o);
                if (!lane) {
                    const float gate = 1.f / (1.f + __expf(-attb[512 + c]));
                    g_xinh[b * 1280 + 256 + c] = gate * s;
                }
            }
            const int tok = caps[b * L_ + t];
            g_xinh[b * 1280 + tid] = emb[(size_t)tok * EMB_ + tid];
            g_xinh[b * 1280 + 768 + tid]       = __ldcg(&g_state[b * 1024 + tid]);
            g_xinh[b * 1280 + 768 + 256 + tid] = __ldcg(&g_state[b * 1024 + 256 + tid]);
        }
        grid_bar();

        // ---- Phase C: gates GEMM (M=64act, N=16, K=1280) + LSTM cell ----
        {
            const int mg = tid >> 4;        // 0..15 (4 m rows each)
            const int ln = tid & 15;        // 0..15 (n' column)
            const int lrow = tid >> 2, lc0 = (tid & 3) * 8;
            float acc[4] = {0.f, 0.f, 0.f, 0.f};
            float4 pa0, pa1;

            // stage chunk 0
            if (lrow < cnt) {
                pa0 = ldcg4(&g_xinh[lrow * 1280 + lc0]);
                pa1 = ldcg4(&g_xinh[lrow * 1280 + lc0 + 4]);
                *reinterpret_cast<float4*>(&scr[lrow * 36 + lc0])     = pa0;
                *reinterpret_cast<float4*>(&scr[lrow * 36 + lc0 + 4]) = pa1;
            }
            __syncthreads();

            int buf = 0;
            for (int ch = 0; ch < 40; ch++) {
                if (ch + 1 < 40 && lrow < cnt) {
                    pa0 = ldcg4(&g_xinh[lrow * 1280 + (ch + 1) * 32 + lc0]);
                    pa1 = ldcg4(&g_xinh[lrow * 1280 + (ch + 1) * 32 + lc0 + 4]);
                }
                if (mg * 4 < cnt) {
                    const float* sA = scr + buf * 2304;
#pragma unroll
                    for (int kk4 = 0; kk4 < 8; kk4++) {
                        float4 w = *reinterpret_cast<const float4*>(
                            &sW[ln * SW_STRIDE + ch * 32 + kk4 * 4]);
#pragma unroll
                        for (int i = 0; i < 4; i++) {
                            float4 a = *reinterpret_cast<const float4*>(
                                &sA[(mg * 4 + i) * 36 + kk4 * 4]);
                            acc[i] = fmaf(a.x, w.x, acc[i]);
                            acc[i] = fmaf(a.y, w.y, acc[i]);
                            acc[i] = fmaf(a.z, w.z, acc[i]);
                            acc[i] = fmaf(a.w, w.w, acc[i]);
                        }
                    }
                }
                if (ch + 1 < 40) {
                    const int nb = buf ^ 1;
                    if (lrow < cnt) {
                        *reinterpret_cast<float4*>(&scr[nb * 2304 + lrow * 36 + lc0])     = pa0;
                        *reinterpret_cast<float4*>(&scr[nb * 2304 + lrow * 36 + lc0 + 4]) = pa1;
                    }
                    __syncthreads();
                    buf = nb;
                }
            }
            __syncthreads();

            // gates -> smem (reuse scratch), then per-(b,d) cell
            float* sG = scr;  // [64][17]
#pragma unroll
            for (int i = 0; i < 4; i++) {
                const int m = mg * 4 + i;
                if (m < cnt) sG[m * 17 + ln] = acc[i];
            }
            __syncthreads();

            const int b2 = tid >> 2, dl = tid & 3;
            if (b2 < cnt) {
                const int nb0 = j * 16 + dl * 4;
                const float gi = sG[b2 * 17 + dl * 4 + 0] + g_blstm[nb0 + 0];
                const float gf = sG[b2 * 17 + dl * 4 + 1] + g_blstm[nb0 + 1];
                const float gg = sG[b2 * 17 + dl * 4 + 2] + g_blstm[nb0 + 2];
                const float go = sG[b2 * 17 + dl * 4 + 3] + g_blstm[nb0 + 3];
                const int d = j * 4 + dl;
                const float cold = __ldcg(&g_state[b2 * 1024 + 512 + d]);
                const float si = 1.f / (1.f + __expf(-gi));
                const float sf = 1.f / (1.f + __expf(-gf));
                const float so = 1.f / (1.f + __expf(-go));
                const float c2 = sf * cold + si * tanhf(gg);
                const float h2 = so * tanhf(c2);
                g_state[b2 * 1024 + d] = h2;
                g_state[b2 * 1024 + 512 + d] = c2;
                g_hall[((size_t)t * B_ + b2) * DEC_ + d] = h2;
            }
        }
        grid_bar();
    }
}

// ============ 64x64 GEMM with bias (h0/c0 init only) =============
__global__ __launch_bounds__(256) void gemm64_kernel(
    const float* __restrict__ A, int lda,
    const float* __restrict__ W, int ldw,
    const float* __restrict__ bias,
    float* __restrict__ C, int ldc, int K)
{
    __shared__ __align__(16) float As[16][64];
    __shared__ __align__(16) float Ws[16][64];
    const int tid = threadIdx.x;
    const int m0 = blockIdx.y * 64;
    const int n0 = blockIdx.x * 64;
    const int lr = tid >> 2;
    const int lk = (tid & 3) << 2;
    const int tx = tid & 15;
    const int ty = tid >> 4;

    float acc[4][4];
#pragma unroll
    for (int i = 0; i < 4; i++)
#pragma unroll
        for (int j = 0; j < 4; j++) acc[i][j] = 0.f;

    const float* aptr = A + (size_t)(m0 + lr) * lda + lk;
    const float* wptr = W + (size_t)(n0 + lr) * ldw + lk;

    for (int k0 = 0; k0 < K; k0 += 16) {
        float4 av = *reinterpret_cast<const float4*>(aptr + k0);
        float4 wv = *reinterpret_cast<const float4*>(wptr + k0);
        As[lk + 0][lr] = av.x; As[lk + 1][lr] = av.y;
        As[lk + 2][lr] = av.z; As[lk + 3][lr] = av.w;
        Ws[lk + 0][lr] = wv.x; Ws[lk + 1][lr] = wv.y;
        Ws[lk + 2][lr] = wv.z; Ws[lk + 3][lr] = wv.w;
        __syncthreads();
#pragma unroll
        for (int kk = 0; kk < 16; kk++) {
            float4 a = *reinterpret_cast<const float4*>(&As[kk][ty << 2]);
            float4 b = *reinterpret_cast<const float4*>(&Ws[kk][tx << 2]);
            float ar[4] = {a.x, a.y, a.z, a.w};
            float br[4] = {b.x, b.y, b.z, b.w};
#pragma unroll
            for (int i = 0; i < 4; i++)
#pragma unroll
                for (int j = 0; j < 4; j++)
                    acc[i][j] = fmaf(ar[i], br[j], acc[i][j]);
        }
        __syncthreads();
    }
    const int n = n0 + (tx << 2);
#pragma unroll
    for (int i = 0; i < 4; i++) {
        const int m = m0 + (ty << 2) + i;
        float4 outv;
        outv.x = acc[i][0] + bias[n + 0];
        outv.y = acc[i][1] + bias[n + 1];
        outv.z = acc[i][2] + bias[n + 2];
        outv.w = acc[i][3] + bias[n + 3];
        *reinterpret_cast<float4*>(&C[(size_t)m * ldc + n]) = outv;
    }
}

// ---------------- prep kernels ----------------
__global__ void prep_weights_kernel(
    const float* __restrict__ Wdec, const float* __restrict__ bdec,
    const float* __restrict__ Wbeta, const float* __restrict__ bbeta,
    const float* __restrict__ Wih, const float* __restrict__ Whh,
    const float* __restrict__ bih, const float* __restrict__ bhh,
    const float* __restrict__ Winith, const float* __restrict__ binith,
    const float* __restrict__ Winitc, const float* __restrict__ binitc)
{
    const int stride = gridDim.x * blockDim.x;
    const int i0 = blockIdx.x * blockDim.x + threadIdx.x;
    for (int i = i0; i < 512 * 512; i += stride) {
        g_Wab[i] = Wdec[i];
        g_Wab[512 * 512 + i] = Wbeta[i];
        g_Winit[i] = Winith[i];
        g_Winit[512 * 512 + i] = Winitc[i];
    }
    for (int i = i0; i < 512; i += stride) {
        g_bab[i] = bdec[i];       g_bab[512 + i] = bbeta[i];
        g_binit[i] = binith[i];   g_binit[512 + i] = binitc[i];
    }
    // Wlstm reordered: row n' = 4*d + gate  (gate-interleaved)
    for (int i = i0; i < 2048 * 1280; i += stride) {
        const int nrow = i / 1280, k = i - nrow * 1280;
        const int d = nrow >> 2, g = nrow & 3;
        const int orig = g * 512 + d;
        g_Wlstm[i] = (k < 768) ? Wih[orig * 768 + k] : Whh[orig * 512 + (k - 768)];
    }
    for (int i = i0; i < 2048; i += stride) {
        const int d = i >> 2, g = i & 3;
        const int orig = g * 512 + d;
        g_blstm[i] = bih[orig] + bhh[orig];
    }
}

__global__ void build_list_kernel(const int* __restrict__ lens)
{
    __shared__ int offs[64];
    const int b = threadIdx.x;
    if (b == 0) {
        int o = 0;
        for (int i = 0; i < B_; i++) { offs[i] = o; o += lens[i] - 1; }
        g_nact = o;
    }
    if (b < T_) {
        int c = 0;
        for (int i = 0; i < B_; i++) c += (lens[i] - 1 > b) ? 1 : 0;
        g_cnt[b] = c;
    }
    __syncthreads();
    if (b < B_) {
        const int o = offs[b];
        const int n = lens[b] - 1;
        for (int t = 0; t < n; t++) g_list[o + t] = (t << 6) | b;
    }
}

__global__ void zerofill_kernel(const int* __restrict__ lens, float* __restrict__ out)
{
    const int b = blockIdx.x / T_;
    const int t = blockIdx.x % T_;
    if (t < lens[b] - 1) return;
    float4 z; z.x = z.y = z.z = z.w = 0.f;
    float4* o = reinterpret_cast<float4*>(out + ((size_t)b * T_ + t) * V_);
    for (int i = threadIdx.x; i < V_ / 4; i += blockDim.x) o[i] = z;
}

__global__ void meanenc_kernel(const float* __restrict__ EO)
{
    const int wg = (blockIdx.x * blockDim.x + threadIdx.x) >> 5;
    const int lane = threadIdx.x & 31;
    if (wg >= B_ * ENC_) return;
    const float* row = EO + (size_t)wg * P_;
    float s = 0.f;
    for (int p = lane; p < P_; p += 32) s += row[p];
#pragma unroll
    for (int o = 16; o; o >>= 1) s += __shfl_xor_sync(0xffffffffu, s, o);
    if (!lane) g_meanenc[wg] = s * (1.0f / P_);
}

// ---------------- launch ----------------
extern "C" void kernel_launch(void* const* d_in, const int* in_sizes, int n_in,
                              void* d_out, int out_size)
{
    const float* EO        = (const float*)d_in[0];
    const int*   caps      = (const int*)  d_in[1];
    const int*   lens      = (const int*)  d_in[2];
    const float* W_enc_att = (const float*)d_in[3];
    const float* b_enc_att = (const float*)d_in[4];
    const float* W_dec_att = (const float*)d_in[5];
    const float* b_dec_att = (const float*)d_in[6];
    const float* w_full    = (const float*)d_in[7];
    const float* b_full    = (const float*)d_in[8];
    const float* emb       = (const float*)d_in[9];
    const float* W_ih      = (const float*)d_in[10];
    const float* W_hh      = (const float*)d_in[11];
    const float* b_ih      = (const float*)d_in[12];
    const float* b_hh      = (const float*)d_in[13];
    const float* W_init_h  = (const float*)d_in[14];
    const float* b_init_h  = (const float*)d_in[15];
    const float* W_init_c  = (const float*)d_in[16];
    const float* b_init_c  = (const float*)d_in[17];
    const float* W_beta    = (const float*)d_in[18];
    const float* b_beta    = (const float*)d_in[19];
    const float* W_fc      = (const float*)d_in[20];
    const float* b_fc      = (const float*)d_in[21];
    float* out = (float*)d_out;

    float *state, *meanenc, *Winit, *binit, *att1;
    __nv_bfloat16 *ench, *encl, *wench, *wencl, *wfch, *wfcl, *afch, *afcl;
    cudaGetSymbolAddress((void**)&state,   g_state);
    cudaGetSymbolAddress((void**)&meanenc, g_meanenc);
    cudaGetSymbolAddress((void**)&Winit,   g_Winit);
    cudaGetSymbolAddress((void**)&binit,   g_binit);
    cudaGetSymbolAddress((void**)&att1,    g_att1);
    cudaGetSymbolAddress((void**)&ench,    g_enc_hi);
    cudaGetSymbolAddress((void**)&encl,    g_enc_lo);
    cudaGetSymbolAddress((void**)&wench,   g_Wenc_hi);
    cudaGetSymbolAddress((void**)&wencl,   g_Wenc_lo);
    cudaGetSymbolAddress((void**)&wfch,    g_Wfc_hi);
    cudaGetSymbolAddress((void**)&wfcl,    g_Wfc_lo);
    cudaGetSymbolAddress((void**)&afch,    g_Afc_hi);
    cudaGetSymbolAddress((void**)&afcl,    g_Afc_lo);

    cudaFuncSetAttribute(step_kernel,
                         cudaFuncAttributeMaxDynamicSharedMemorySize, STEP_SMEM);

    // ---- one-time prep ----
    prep_weights_kernel<<<512, 256>>>(W_dec_att, b_dec_att, W_beta, b_beta,
                                      W_ih, W_hh, b_ih, b_hh,
                                      W_init_h, b_init_h, W_init_c, b_init_c);
    build_list_kernel<<<1, 64>>>(lens);
    zerofill_kernel<<<B_ * T_, 256>>>(lens, out);
    meanenc_kernel<<<4096, 256>>>(EO);
    gemm64_kernel<<<dim3(16, 1), 256>>>(meanenc, 512, Winit, 512, binit,
                                        state, 1024, 512);

    // bf16 conversions for tensor-core GEMMs
    conv_split_kernel<<<512, 256>>>(W_enc_att, wench, wencl, ATT_ * ENC_);
    conv_enc_kernel<<<dim3(8, 16, 64), dim3(32, 8)>>>(EO);
    conv_split_kernel<<<4096, 256>>>(W_fc, wfch, wfcl, V_ * DEC_);

    // att1 = enc @ W_enc_att^T + b  via HMMA
    mma_gemm_kernel<<<dim3(4, 128), 256>>>(ench, encl, wench, wencl,
                                           b_enc_att, att1, ATT_, 0);

    // ---- full decode recurrence in ONE persistent kernel ----
    step_kernel<<<NB_, 256, STEP_SMEM>>>(EO, emb, caps, w_full, b_full);

    // ---- fc on gathered active rows via HMMA ----
    conv_fcA_kernel<<<MROWS_FC, 256>>>();
    mma_gemm_kernel<<<dim3(125, 16), 256>>>(afch, afcl, wfch, wfcl,
                                            b_fc, out, V_, 1);
}

// round 15
// speedup vs baseline: 1.5340x; 1.1450x over previous
#include <cuda_runtime.h>
#include <cstdint>

#define B_   64
#define L_   32
#define T_   31
#define V_   16000
#define ENC_ 512
#define DEC_ 512
#define ATT_ 512
#define EMB_ 256
#define P_   256

#define NB_    128
#define MROWS_FC 2048

// step_kernel dynamic smem layout (floats)
#define SW_STRIDE 1284
#define OFF_SW    0                       // 16 x 1284 = 20544
#define OFF_SWAB  20544                   // 8 x 516   = 4128
#define OFF_WS    24672                   // 512
#define OFF_SCR   25184                   // 4608 scratch
#define STEP_SMEM ((25184 + 4608) * 4)    // 119168 bytes

// ---------------- device scratch ----------------
__device__ float g_state[B_ * 1024];
__device__ float g_meanenc[B_ * ENC_];
__device__ float g_att1[B_ * P_ * ATT_];
__device__ float g_Wab[1024 * 512];
__device__ float g_bab[1024];
__device__ float g_Winit[1024 * 512];
__device__ float g_binit[1024];
__device__ float g_Wlstm[2048 * 1280];    // row n' = 4*d + gate
__device__ float g_blstm[2048];
__device__ float g_ab[B_ * 1024];
__device__ float g_xinh[B_ * 1280];
__device__ float g_hall[T_ * B_ * DEC_];
__device__ int   g_list[T_ * B_];
__device__ int   g_nact;
__device__ int   g_cnt[T_];
__device__ unsigned g_bar_count = 0;
__device__ unsigned g_bar_gen   = 0;

__device__ __forceinline__ float4 ldcg4(const float* p) {
    return __ldcg(reinterpret_cast<const float4*>(p));
}

// ---------------- software grid barrier (bare poll) ----------------
__device__ __forceinline__ void grid_bar() {
    __syncthreads();
    if (threadIdx.x == 0) {
        __threadfence();
        unsigned gen = *((volatile unsigned*)&g_bar_gen);
        unsigned t = atomicAdd(&g_bar_count, 1u);
        if (t == NB_ - 1) {
            g_bar_count = 0;
            __threadfence();
            *((volatile unsigned*)&g_bar_gen) = gen + 1;
        } else {
            while (*((volatile unsigned*)&g_bar_gen) == gen) { }
        }
    }
    __syncthreads();
}

// ================= persistent decode-loop kernel =================
// Phase A (128 blocks): ab = h @ Wab^T + bab (weights smem-resident)
// Phase B (cnt blocks): attention + softmax + gated awe -> xinh (4-way ILP)
// Phase C (128 blocks): gates full-K GEMM (W' smem-resident) + LSTM cell
__global__ __launch_bounds__(256, 1) void step_kernel(
    const float* __restrict__ EO, const float* __restrict__ emb,
    const int* __restrict__ caps, const float* __restrict__ wfull,
    const float* __restrict__ bfull)
{
    extern __shared__ float dsm[];
    float* sW   = dsm + OFF_SW;
    float* sWab = dsm + OFF_SWAB;
    float* ws   = dsm + OFF_WS;
    float* scr  = dsm + OFF_SCR;

    const int tid = threadIdx.x;
    const int lane = tid & 31, warp = tid >> 5;
    const int j = blockIdx.x;

    // ---- one-time staging ----
#pragma unroll
    for (int r = 0; r < 16; r++)
        for (int k = tid * 4; k < 1280; k += 1024)
            *reinterpret_cast<float4*>(&sW[r * SW_STRIDE + k]) =
                *reinterpret_cast<const float4*>(&g_Wlstm[(size_t)(j * 16 + r) * 1280 + k]);
    for (int i = tid; i < 8 * 512; i += 256) {
        const int r = i >> 9, c = i & 511;
        sWab[r * 516 + c] = g_Wab[(size_t)(j * 8 + r) * 512 + c];
    }
    ws[tid] = wfull[tid];
    ws[tid + 256] = wfull[tid + 256];
    __syncthreads();

    for (int t = 0; t < T_; t++) {
        const int cnt = __ldg(&g_cnt[t]);

        // ---- Phase A ----
        {
            const int b = tid >> 2;
            if (b < cnt) {
                const int nl0 = (tid & 3) << 1;
                const float* hb = g_state + b * 1024;
                const float* w0p = sWab + nl0 * 516;
                const float* w1p = sWab + (nl0 + 1) * 516;
                float4 s0 = {0.f,0.f,0.f,0.f}, s1 = {0.f,0.f,0.f,0.f};
#pragma unroll 4
                for (int k = 0; k < 512; k += 4) {
                    float4 hv = ldcg4(hb + k);
                    float4 w0 = *reinterpret_cast<const float4*>(w0p + k);
                    float4 w1 = *reinterpret_cast<const float4*>(w1p + k);
                    s0.x = fmaf(hv.x, w0.x, s0.x); s0.y = fmaf(hv.y, w0.y, s0.y);
                    s0.z = fmaf(hv.z, w0.z, s0.z); s0.w = fmaf(hv.w, w0.w, s0.w);
                    s1.x = fmaf(hv.x, w1.x, s1.x); s1.y = fmaf(hv.y, w1.y, s1.y);
                    s1.z = fmaf(hv.z, w1.z, s1.z); s1.w = fmaf(hv.w, w1.w, s1.w);
                }
                const int n0 = j * 8;
                g_ab[b * 1024 + n0 + nl0]     = s0.x + s0.y + s0.z + s0.w + g_bab[n0 + nl0];
                g_ab[b * 1024 + n0 + nl0 + 1] = s1.x + s1.y + s1.z + s1.w + g_bab[n0 + nl0 + 1];
            }
        }
        grid_bar();

        // ---- Phase B (4-way ILP) ----
        if (j < cnt) {
            const int b = j;
            float* attb = scr;               // 1024
            float* es   = scr + 1024;        // 256
            float* red  = scr + 1280;        // 8
            float* sv   = scr + 1288;        // 1
            float4* attb4 = reinterpret_cast<float4*>(attb);
            float4* es4   = reinterpret_cast<float4*>(es);
            float4* ws4   = reinterpret_cast<float4*>(ws);

            attb4[tid] = ldcg4(&g_ab[b * 1024 + tid * 4]);
            __syncthreads();

            const float bf = bfull[0];
            // energies: 4 p per warp concurrently (8 sweeps)
            for (int p0 = warp * 4; p0 < 256; p0 += 32) {
                const float4* r0 = reinterpret_cast<const float4*>(
                    g_att1 + ((size_t)b * 256 + p0) * 512);
                float s0 = 0.f, s1 = 0.f, s2 = 0.f, s3 = 0.f;
#pragma unroll
                for (int i = 0; i < 4; i++) {
                    const int idx = lane + i * 32;
                    float4 a2 = attb4[idx];
                    float4 wv = ws4[idx];
                    float4 v0 = __ldg(r0 + idx);
                    float4 v1 = __ldg(r0 + 128 + idx);
                    float4 v2 = __ldg(r0 + 256 + idx);
                    float4 v3 = __ldg(r0 + 384 + idx);
                    s0 = fmaf(fmaxf(v0.x + a2.x, 0.f), wv.x, s0);
                    s0 = fmaf(fmaxf(v0.y + a2.y, 0.f), wv.y, s0);
                    s0 = fmaf(fmaxf(v0.z + a2.z, 0.f), wv.z, s0);
                    s0 = fmaf(fmaxf(v0.w + a2.w, 0.f), wv.w, s0);
                    s1 = fmaf(fmaxf(v1.x + a2.x, 0.f), wv.x, s1);
                    s1 = fmaf(fmaxf(v1.y + a2.y, 0.f), wv.y, s1);
                    s1 = fmaf(fmaxf(v1.z + a2.z, 0.f), wv.z, s1);
                    s1 = fmaf(fmaxf(v1.w + a2.w, 0.f), wv.w, s1);
                    s2 = fmaf(fmaxf(v2.x + a2.x, 0.f), wv.x, s2);
                    s2 = fmaf(fmaxf(v2.y + a2.y, 0.f), wv.y, s2);
                    s2 = fmaf(fmaxf(v2.z + a2.z, 0.f), wv.z, s2);
                    s2 = fmaf(fmaxf(v2.w + a2.w, 0.f), wv.w, s2);
                    s3 = fmaf(fmaxf(v3.x + a2.x, 0.f), wv.x, s3);
                    s3 = fmaf(fmaxf(v3.y + a2.y, 0.f), wv.y, s3);
                    s3 = fmaf(fmaxf(v3.z + a2.z, 0.f), wv.z, s3);
                    s3 = fmaf(fmaxf(v3.w + a2.w, 0.f), wv.w, s3);
                }
#pragma unroll
                for (int o = 16; o; o >>= 1) {
                    s0 += __shfl_xor_sync(0xffffffffu, s0, o);
                    s1 += __shfl_xor_sync(0xffffffffu, s1, o);
                    s2 += __shfl_xor_sync(0xffffffffu, s2, o);
                    s3 += __shfl_xor_sync(0xffffffffu, s3, o);
                }
                if (!lane) {
                    es[p0 + 0] = s0 + bf;
                    es[p0 + 1] = s1 + bf;
                    es[p0 + 2] = s2 + bf;
                    es[p0 + 3] = s3 + bf;
                }
            }
            __syncthreads();

            // softmax
            float v = es[tid];
            float mx = v;
#pragma unroll
            for (int o = 16; o; o >>= 1) mx = fmaxf(mx, __shfl_xor_sync(0xffffffffu, mx, o));
            if (!lane) red[warp] = mx;
            __syncthreads();
            if (tid == 0) {
                float mm = red[0];
#pragma unroll
                for (int i = 1; i < 8; i++) mm = fmaxf(mm, red[i]);
                sv[0] = mm;
            }
            __syncthreads();
            float ex = __expf(v - sv[0]);
            float s2r = ex;
#pragma unroll
            for (int o = 16; o; o >>= 1) s2r += __shfl_xor_sync(0xffffffffu, s2r, o);
            if (!lane) red[warp] = s2r;
            __syncthreads();
            if (tid == 0) {
                float ss = 0.f;
#pragma unroll
                for (int i = 0; i < 8; i++) ss += red[i];
                sv[0] = ss;
            }
            __syncthreads();
            es[tid] = ex / sv[0];
            __syncthreads();

            // awe: 4 c per warp concurrently (16 sweeps)
            for (int c0 = warp * 4; c0 < 512; c0 += 32) {
                const float4* e0 = reinterpret_cast<const float4*>(
                    EO + ((size_t)b * 512 + c0) * 256);
                float s0 = 0.f, s1 = 0.f, s2 = 0.f, s3 = 0.f;
#pragma unroll
                for (int i = 0; i < 2; i++) {
                    const int idx = lane + i * 32;
                    float4 al = es4[idx];
                    float4 v0 = __ldg(e0 + idx);
                    float4 v1 = __ldg(e0 + 64 + idx);
                    float4 v2 = __ldg(e0 + 128 + idx);
                    float4 v3 = __ldg(e0 + 192 + idx);
                    s0 = fmaf(al.x, v0.x, s0); s0 = fmaf(al.y, v0.y, s0);
                    s0 = fmaf(al.z, v0.z, s0); s0 = fmaf(al.w, v0.w, s0);
                    s1 = fmaf(al.x, v1.x, s1); s1 = fmaf(al.y, v1.y, s1);
                    s1 = fmaf(al.z, v1.z, s1); s1 = fmaf(al.w, v1.w, s1);
                    s2 = fmaf(al.x, v2.x, s2); s2 = fmaf(al.y, v2.y, s2);
                    s2 = fmaf(al.z, v2.z, s2); s2 = fmaf(al.w, v2.w, s2);
                    s3 = fmaf(al.x, v3.x, s3); s3 = fmaf(al.y, v3.y, s3);
                    s3 = fmaf(al.z, v3.z, s3); s3 = fmaf(al.w, v3.w, s3);
                }
#pragma unroll
                for (int o = 16; o; o >>= 1) {
                    s0 += __shfl_xor_sync(0xffffffffu, s0, o);
                    s1 += __shfl_xor_sync(0xffffffffu, s1, o);
                    s2 += __shfl_xor_sync(0xffffffffu, s2, o);
                    s3 += __shfl_xor_sync(0xffffffffu, s3, o);
                }
                if (!lane) {
                    const float g0 = 1.f / (1.f + __expf(-attb[512 + c0 + 0]));
                    const float g1 = 1.f / (1.f + __expf(-attb[512 + c0 + 1]));
                    const float g2 = 1.f / (1.f + __expf(-attb[512 + c0 + 2]));
                    const float g3 = 1.f / (1.f + __expf(-attb[512 + c0 + 3]));
                    g_xinh[b * 1280 + 256 + c0 + 0] = g0 * s0;
                    g_xinh[b * 1280 + 256 + c0 + 1] = g1 * s1;
                    g_xinh[b * 1280 + 256 + c0 + 2] = g2 * s2;
                    g_xinh[b * 1280 + 256 + c0 + 3] = g3 * s3;
                }
            }
            const int tok = caps[b * L_ + t];
            g_xinh[b * 1280 + tid] = emb[(size_t)tok * EMB_ + tid];
            g_xinh[b * 1280 + 768 + tid]       = __ldcg(&g_state[b * 1024 + tid]);
            g_xinh[b * 1280 + 768 + 256 + tid] = __ldcg(&g_state[b * 1024 + 256 + tid]);
        }
        grid_bar();

        // ---- Phase C: gates GEMM + LSTM cell ----
        {
            const int mg = tid >> 4;
            const int ln = tid & 15;
            const int lrow = tid >> 2, lc0 = (tid & 3) * 8;
            float acc[4] = {0.f, 0.f, 0.f, 0.f};
            float4 pa0, pa1;

            if (lrow < cnt) {
                pa0 = ldcg4(&g_xinh[lrow * 1280 + lc0]);
                pa1 = ldcg4(&g_xinh[lrow * 1280 + lc0 + 4]);
                *reinterpret_cast<float4*>(&scr[lrow * 36 + lc0])     = pa0;
                *reinterpret_cast<float4*>(&scr[lrow * 36 + lc0 + 4]) = pa1;
            }
            __syncthreads();

            int buf = 0;
            for (int ch = 0; ch < 40; ch++) {
                if (ch + 1 < 40 && lrow < cnt) {
                    pa0 = ldcg4(&g_xinh[lrow * 1280 + (ch + 1) * 32 + lc0]);
                    pa1 = ldcg4(&g_xinh[lrow * 1280 + (ch + 1) * 32 + lc0 + 4]);
                }
                if (mg * 4 < cnt) {
                    const float* sA = scr + buf * 2304;
#pragma unroll
                    for (int kk4 = 0; kk4 < 8; kk4++) {
                        float4 w = *reinterpret_cast<const float4*>(
                            &sW[ln * SW_STRIDE + ch * 32 + kk4 * 4]);
#pragma unroll
                        for (int i = 0; i < 4; i++) {
                            float4 a = *reinterpret_cast<const float4*>(
                                &sA[(mg * 4 + i) * 36 + kk4 * 4]);
                            acc[i] = fmaf(a.x, w.x, acc[i]);
                            acc[i] = fmaf(a.y, w.y, acc[i]);
                            acc[i] = fmaf(a.z, w.z, acc[i]);
                            acc[i] = fmaf(a.w, w.w, acc[i]);
                        }
                    }
                }
                if (ch + 1 < 40) {
                    const int nb = buf ^ 1;
                    if (lrow < cnt) {
                        *reinterpret_cast<float4*>(&scr[nb * 2304 + lrow * 36 + lc0])     = pa0;
                        *reinterpret_cast<float4*>(&scr[nb * 2304 + lrow * 36 + lc0 + 4]) = pa1;
                    }
                    __syncthreads();
                    buf = nb;
                }
            }
            __syncthreads();

            float* sG = scr;  // [64][17]
#pragma unroll
            for (int i = 0; i < 4; i++) {
                const int m = mg * 4 + i;
                if (m < cnt) sG[m * 17 + ln] = acc[i];
            }
            __syncthreads();

            const int b2 = tid >> 2, dl = tid & 3;
            if (b2 < cnt) {
                const int nb0 = j * 16 + dl * 4;
                const float gi = sG[b2 * 17 + dl * 4 + 0] + g_blstm[nb0 + 0];
                const float gf = sG[b2 * 17 + dl * 4 + 1] + g_blstm[nb0 + 1];
                const float gg = sG[b2 * 17 + dl * 4 + 2] + g_blstm[nb0 + 2];
                const float go = sG[b2 * 17 + dl * 4 + 3] + g_blstm[nb0 + 3];
                const int d = j * 4 + dl;
                const float cold = __ldcg(&g_state[b2 * 1024 + 512 + d]);
                const float si = 1.f / (1.f + __expf(-gi));
                const float sf = 1.f / (1.f + __expf(-gf));
                const float so = 1.f / (1.f + __expf(-go));
                const float c2 = sf * cold + si * tanhf(gg);
                const float h2 = so * tanhf(c2);
                g_state[b2 * 1024 + d] = h2;
                g_state[b2 * 1024 + 512 + d] = c2;
                g_hall[((size_t)t * B_ + b2) * DEC_ + d] = h2;
            }
        }
        grid_bar();
    }
}

// ================= fp32 128x128 / 8x8 double-buffered GEMMs =================
// att1: C[m][n] = sum_k EO[b][k][p] * W[n][k] + bias[n], m = b*256 + p
__global__ __launch_bounds__(256) void att1_gemm_kernel(
    const float* __restrict__ EO, const float* __restrict__ W,
    const float* __restrict__ bias)
{
    __shared__ __align__(16) float As[2][16][136];
    __shared__ __align__(16) float Bs[2][16][136];
    const int tid = threadIdx.x;
    const int tx = tid & 15, ty = tid >> 4;
    const int n0 = blockIdx.x * 128;
    const int m0 = blockIdx.y * 128;
    const int b  = blockIdx.y >> 1;
    const int p0 = (blockIdx.y & 1) * 128;
    const int ia = tid * 2;

    float acc[8][8];
#pragma unroll
    for (int i = 0; i < 8; i++)
#pragma unroll
        for (int j = 0; j < 8; j++) acc[i][j] = 0.f;

    float4 va[2], vb[2];
#pragma unroll
    for (int j = 0; j < 2; j++) {
        const int i = ia + j;
        const int k = i >> 5, p = (i & 31) << 2;
        va[j] = *reinterpret_cast<const float4*>(
            EO + ((size_t)b * 512 + k) * 256 + p0 + p);
        const int nr = i >> 2, kc = (i & 3) << 2;
        vb[j] = *reinterpret_cast<const float4*>(W + (size_t)(n0 + nr) * 512 + kc);
    }
#pragma unroll
    for (int j = 0; j < 2; j++) {
        const int i = ia + j;
        const int k = i >> 5, p = (i & 31) << 2;
        *reinterpret_cast<float4*>(&As[0][k][p]) = va[j];
        const int nr = i >> 2, kc = (i & 3) << 2;
        Bs[0][kc + 0][nr] = vb[j].x; Bs[0][kc + 1][nr] = vb[j].y;
        Bs[0][kc + 2][nr] = vb[j].z; Bs[0][kc + 3][nr] = vb[j].w;
    }
    __syncthreads();

    int buf = 0;
    for (int s = 0; s < 32; s++) {
        const int kn = (s + 1) * 16;
        if (s + 1 < 32) {
#pragma unroll
            for (int j = 0; j < 2; j++) {
                const int i = ia + j;
                const int k = i >> 5, p = (i & 31) << 2;
                va[j] = *reinterpret_cast<const float4*>(
                    EO + ((size_t)b * 512 + kn + k) * 256 + p0 + p);
                const int nr = i >> 2, kc = (i & 3) << 2;
                vb[j] = *reinterpret_cast<const float4*>(
                    W + (size_t)(n0 + nr) * 512 + kn + kc);
            }
        }
#pragma unroll
        for (int kk = 0; kk < 16; kk++) {
            float4 a0 = *reinterpret_cast<const float4*>(&As[buf][kk][ty << 3]);
            float4 a1 = *reinterpret_cast<const float4*>(&As[buf][kk][(ty << 3) + 4]);
            float4 b0 = *reinterpret_cast<const float4*>(&Bs[buf][kk][tx << 3]);
            float4 b1 = *reinterpret_cast<const float4*>(&Bs[buf][kk][(tx << 3) + 4]);
            float ar[8] = {a0.x, a0.y, a0.z, a0.w, a1.x, a1.y, a1.z, a1.w};
            float br[8] = {b0.x, b0.y, b0.z, b0.w, b1.x, b1.y, b1.z, b1.w};
#pragma unroll
            for (int i = 0; i < 8; i++)
#pragma unroll
                for (int j = 0; j < 8; j++)
                    acc[i][j] = fmaf(ar[i], br[j], acc[i][j]);
        }
        if (s + 1 < 32) {
            const int nb = buf ^ 1;
#pragma unroll
            for (int j = 0; j < 2; j++) {
                const int i = ia + j;
                const int k = i >> 5, p = (i & 31) << 2;
                *reinterpret_cast<float4*>(&As[nb][k][p]) = va[j];
                const int nr = i >> 2, kc = (i & 3) << 2;
                Bs[nb][kc + 0][nr] = vb[j].x; Bs[nb][kc + 1][nr] = vb[j].y;
                Bs[nb][kc + 2][nr] = vb[j].z; Bs[nb][kc + 3][nr] = vb[j].w;
            }
            __syncthreads();
            buf = nb;
        }
    }

    float bi[8];
#pragma unroll
    for (int j = 0; j < 8; j++) bi[j] = bias[n0 + (tx << 3) + j];
#pragma unroll
    for (int i = 0; i < 8; i++) {
        float* cr = g_att1 + (size_t)(m0 + (ty << 3) + i) * 512 + n0 + (tx << 3);
        float4 o0, o1;
        o0.x = acc[i][0] + bi[0]; o0.y = acc[i][1] + bi[1];
        o0.z = acc[i][2] + bi[2]; o0.w = acc[i][3] + bi[3];
        o1.x = acc[i][4] + bi[4]; o1.y = acc[i][5] + bi[5];
        o1.z = acc[i][6] + bi[6]; o1.w = acc[i][7] + bi[7];
        *reinterpret_cast<float4*>(cr) = o0;
        *reinterpret_cast<float4*>(cr + 4) = o1;
    }
}

// fc: active rows gathered via g_list; out[b][t][:] = hall_row @ W_fc^T + b_fc
__global__ __launch_bounds__(256) void fc_gemm_kernel(
    const float* __restrict__ W, const float* __restrict__ bias,
    float* __restrict__ out)
{
    const int nact = g_nact;
    const int m0 = blockIdx.y * 128;
    if (m0 >= nact) return;

    __shared__ __align__(16) float As[2][16][136];
    __shared__ __align__(16) float Bs[2][16][136];
    const int tid = threadIdx.x;
    const int tx = tid & 15, ty = tid >> 4;
    const int n0 = blockIdx.x * 128;
    const int ia = tid * 2;

    const float* aRow[2];
#pragma unroll
    for (int j = 0; j < 2; j++) {
        const int i = ia + j;
        int r = m0 + (i >> 2);
        if (r > nact - 1) r = nact - 1;
        aRow[j] = g_hall + (size_t)g_list[r] * DEC_ + ((i & 3) << 2);
    }

    float acc[8][8];
#pragma unroll
    for (int i = 0; i < 8; i++)
#pragma unroll
        for (int j = 0; j < 8; j++) acc[i][j] = 0.f;

    float4 va[2], vb[2];
#pragma unroll
    for (int j = 0; j < 2; j++) {
        const int i = ia + j;
        va[j] = *reinterpret_cast<const float4*>(aRow[j]);
        const int nr = i >> 2, kc = (i & 3) << 2;
        vb[j] = *reinterpret_cast<const float4*>(W + (size_t)(n0 + nr) * 512 + kc);
    }
#pragma unroll
    for (int j = 0; j < 2; j++) {
        const int i = ia + j;
        const int mr = i >> 2, kc = (i & 3) << 2;
        As[0][kc + 0][mr] = va[j].x; As[0][kc + 1][mr] = va[j].y;
        As[0][kc + 2][mr] = va[j].z; As[0][kc + 3][mr] = va[j].w;
        Bs[0][kc + 0][mr] = vb[j].x; Bs[0][kc + 1][mr] = vb[j].y;
        Bs[0][kc + 2][mr] = vb[j].z; Bs[0][kc + 3][mr] = vb[j].w;
    }
    __syncthreads();

    int buf = 0;
    for (int s = 0; s < 32; s++) {
        const int kn = (s + 1) * 16;
        if (s + 1 < 32) {
#pragma unroll
            for (int j = 0; j < 2; j++) {
                const int i = ia + j;
                va[j] = *reinterpret_cast<const float4*>(aRow[j] + kn);
                const int nr = i >> 2, kc = (i & 3) << 2;
                vb[j] = *reinterpret_cast<const float4*>(
                    W + (size_t)(n0 + nr) * 512 + kn + kc);
            }
        }
#pragma unroll
        for (int kk = 0; kk < 16; kk++) {
            float4 a0 = *reinterpret_cast<const float4*>(&As[buf][kk][ty << 3]);
            float4 a1 = *reinterpret_cast<const float4*>(&As[buf][kk][(ty << 3) + 4]);
            float4 b0 = *reinterpret_cast<const float4*>(&Bs[buf][kk][tx << 3]);
            float4 b1 = *reinterpret_cast<const float4*>(&Bs[buf][kk][(tx << 3) + 4]);
            float ar[8] = {a0.x, a0.y, a0.z, a0.w, a1.x, a1.y, a1.z, a1.w};
            float br[8] = {b0.x, b0.y, b0.z, b0.w, b1.x, b1.y, b1.z, b1.w};
#pragma unroll
            for (int i = 0; i < 8; i++)
#pragma unroll
                for (int j = 0; j < 8; j++)
                    acc[i][j] = fmaf(ar[i], br[j], acc[i][j]);
        }
        if (s + 1 < 32) {
            const int nb = buf ^ 1;
#pragma unroll
            for (int j = 0; j < 2; j++) {
                const int i = ia + j;
                const int mr = i >> 2, kc = (i & 3) << 2;
                As[nb][kc + 0][mr] = va[j].x; As[nb][kc + 1][mr] = va[j].y;
                As[nb][kc + 2][mr] = va[j].z; As[nb][kc + 3][mr] = va[j].w;
                Bs[nb][kc + 0][mr] = vb[j].x; Bs[nb][kc + 1][mr] = vb[j].y;
                Bs[nb][kc + 2][mr] = vb[j].z; Bs[nb][kc + 3][mr] = vb[j].w;
            }
            __syncthreads();
            buf = nb;
        }
    }

    float bi[8];
#pragma unroll
    for (int j = 0; j < 8; j++) bi[j] = bias[n0 + (tx << 3) + j];
#pragma unroll
    for (int i = 0; i < 8; i++) {
        const int r = m0 + (ty << 3) + i;
        if (r < nact) {
            const int v = g_list[r];
            const int b = v & 63, t = v >> 6;
            float* cr = out + ((size_t)b * T_ + t) * V_ + n0 + (tx << 3);
            float4 o0, o1;
            o0.x = acc[i][0] + bi[0]; o0.y = acc[i][1] + bi[1];
            o0.z = acc[i][2] + bi[2]; o0.w = acc[i][3] + bi[3];
            o1.x = acc[i][4] + bi[4]; o1.y = acc[i][5] + bi[5];
            o1.z = acc[i][6] + bi[6]; o1.w = acc[i][7] + bi[7];
            *reinterpret_cast<float4*>(cr) = o0;
            *reinterpret_cast<float4*>(cr + 4) = o1;
        }
    }
}

// ============ 64x64 GEMM with bias (h0/c0 init only) =============
__global__ __launch_bounds__(256) void gemm64_kernel(
    const float* __restrict__ A, int lda,
    const float* __restrict__ W, int ldw,
    const float* __restrict__ bias,
    float* __restrict__ C, int ldc, int K)
{
    __shared__ __align__(16) float As[16][64];
    __shared__ __align__(16) float Ws[16][64];
    const int tid = threadIdx.x;
    const int m0 = blockIdx.y * 64;
    const int n0 = blockIdx.x * 64;
    const int lr = tid >> 2;
    const int lk = (tid & 3) << 2;
    const int tx = tid & 15;
    const int ty = tid >> 4;

    float acc[4][4];
#pragma unroll
    for (int i = 0; i < 4; i++)
#pragma unroll
        for (int j = 0; j < 4; j++) acc[i][j] = 0.f;

    const float* aptr = A + (size_t)(m0 + lr) * lda + lk;
    const float* wptr = W + (size_t)(n0 + lr) * ldw + lk;

    for (int k0 = 0; k0 < K; k0 += 16) {
        float4 av = *reinterpret_cast<const float4*>(aptr + k0);
        float4 wv = *reinterpret_cast<const float4*>(wptr + k0);
        As[lk + 0][lr] = av.x; As[lk + 1][lr] = av.y;
        As[lk + 2][lr] = av.z; As[lk + 3][lr] = av.w;
        Ws[lk + 0][lr] = wv.x; Ws[lk + 1][lr] = wv.y;
        Ws[lk + 2][lr] = wv.z; Ws[lk + 3][lr] = wv.w;
        __syncthreads();
#pragma unroll
        for (int kk = 0; kk < 16; kk++) {
            float4 a = *reinterpret_cast<const float4*>(&As[kk][ty << 2]);
            float4 b = *reinterpret_cast<const float4*>(&Ws[kk][tx << 2]);
            float ar[4] = {a.x, a.y, a.z, a.w};
            float br[4] = {b.x, b.y, b.z, b.w};
#pragma unroll
            for (int i = 0; i < 4; i++)
#pragma unroll
                for (int j = 0; j < 4; j++)
                    acc[i][j] = fmaf(ar[i], br[j], acc[i][j]);
        }
        __syncthreads();
    }
    const int n = n0 + (tx << 2);
#pragma unroll
    for (int i = 0; i < 4; i++) {
        const int m = m0 + (ty << 2) + i;
        float4 outv;
        outv.x = acc[i][0] + bias[n + 0];
        outv.y = acc[i][1] + bias[n + 1];
        outv.z = acc[i][2] + bias[n + 2];
        outv.w = acc[i][3] + bias[n + 3];
        *reinterpret_cast<float4*>(&C[(size_t)m * ldc + n]) = outv;
    }
}

// ---------------- prep kernels ----------------
__global__ void prep_weights_kernel(
    const float* __restrict__ Wdec, const float* __restrict__ bdec,
    const float* __restrict__ Wbeta, const float* __restrict__ bbeta,
    const float* __restrict__ Wih, const float* __restrict__ Whh,
    const float* __restrict__ bih, const float* __restrict__ bhh,
    const float* __restrict__ Winith, const float* __restrict__ binith,
    const float* __restrict__ Winitc, const float* __restrict__ binitc)
{
    const int stride = gridDim.x * blockDim.x;
    const int i0 = blockIdx.x * blockDim.x + threadIdx.x;
    for (int i = i0; i < 512 * 512; i += stride) {
        g_Wab[i] = Wdec[i];
        g_Wab[512 * 512 + i] = Wbeta[i];
        g_Winit[i] = Winith[i];
        g_Winit[512 * 512 + i] = Winitc[i];
    }
    for (int i = i0; i < 512; i += stride) {
        g_bab[i] = bdec[i];       g_bab[512 + i] = bbeta[i];
        g_binit[i] = binith[i];   g_binit[512 + i] = binitc[i];
    }
    // Wlstm reordered: row n' = 4*d + gate
    for (int i = i0; i < 2048 * 1280; i += stride) {
        const int nrow = i / 1280, k = i - nrow * 1280;
        const int d = nrow >> 2, g = nrow & 3;
        const int orig = g * 512 + d;
        g_Wlstm[i] = (k < 768) ? Wih[orig * 768 + k] : Whh[orig * 512 + (k - 768)];
    }
    for (int i = i0; i < 2048; i += stride) {
        const int d = i >> 2, g = i & 3;
        const int orig = g * 512 + d;
        g_blstm[i] = bih[orig] + bhh[orig];
    }
}

__global__ void build_list_kernel(const int* __restrict__ lens)
{
    __shared__ int offs[64];
    const int b = threadIdx.x;
    if (b == 0) {
        int o = 0;
        for (int i = 0; i < B_; i++) { offs[i] = o; o += lens[i] - 1; }
        g_nact = o;
    }
    if (b < T_) {
        int c = 0;
        for (int i = 0; i < B_; i++) c += (lens[i] - 1 > b) ? 1 : 0;
        g_cnt[b] = c;
    }
    __syncthreads();
    if (b < B_) {
        const int o = offs[b];
        const int n = lens[b] - 1;
        for (int t = 0; t < n; t++) g_list[o + t] = (t << 6) | b;
    }
}

__global__ void zerofill_kernel(const int* __restrict__ lens, float* __restrict__ out)
{
    const int b = blockIdx.x / T_;
    const int t = blockIdx.x % T_;
    if (t < lens[b] - 1) return;
    float4 z; z.x = z.y = z.z = z.w = 0.f;
    float4* o = reinterpret_cast<float4*>(out + ((size_t)b * T_ + t) * V_);
    for (int i = threadIdx.x; i < V_ / 4; i += blockDim.x) o[i] = z;
}

__global__ void meanenc_kernel(const float* __restrict__ EO)
{
    const int wg = (blockIdx.x * blockDim.x + threadIdx.x) >> 5;
    const int lane = threadIdx.x & 31;
    if (wg >= B_ * ENC_) return;
    const float* row = EO + (size_t)wg * P_;
    float s = 0.f;
    for (int p = lane; p < P_; p += 32) s += row[p];
#pragma unroll
    for (int o = 16; o; o >>= 1) s += __shfl_xor_sync(0xffffffffu, s, o);
    if (!lane) g_meanenc[wg] = s * (1.0f / P_);
}

// ---------------- launch ----------------
extern "C" void kernel_launch(void* const* d_in, const int* in_sizes, int n_in,
                              void* d_out, int out_size)
{
    const float* EO        = (const float*)d_in[0];
    const int*   caps      = (const int*)  d_in[1];
    const int*   lens      = (const int*)  d_in[2];
    const float* W_enc_att = (const float*)d_in[3];
    const float* b_enc_att = (const float*)d_in[4];
    const float* W_dec_att = (const float*)d_in[5];
    const float* b_dec_att = (const float*)d_in[6];
    const float* w_full    = (const float*)d_in[7];
    const float* b_full    = (const float*)d_in[8];
    const float* emb       = (const float*)d_in[9];
    const float* W_ih      = (const float*)d_in[10];
    const float* W_hh      = (const float*)d_in[11];
    const float* b_ih      = (const float*)d_in[12];
    const float* b_hh      = (const float*)d_in[13];
    const float* W_init_h  = (const float*)d_in[14];
    const float* b_init_h  = (const float*)d_in[15];
    const float* W_init_c  = (const float*)d_in[16];
    const float* b_init_c  = (const float*)d_in[17];
    const float* W_beta    = (const float*)d_in[18];
    const float* b_beta    = (const float*)d_in[19];
    const float* W_fc      = (const float*)d_in[20];
    const float* b_fc      = (const float*)d_in[21];
    float* out = (float*)d_out;

    float *state, *meanenc, *Winit, *binit;
    cudaGetSymbolAddress((void**)&state,   g_state);
    cudaGetSymbolAddress((void**)&meanenc, g_meanenc);
    cudaGetSymbolAddress((void**)&Winit,   g_Winit);
    cudaGetSymbolAddress((void**)&binit,   g_binit);

    cudaFuncSetAttribute(step_kernel,
                         cudaFuncAttributeMaxDynamicSharedMemorySize, STEP_SMEM);

    // ---- one-time prep ----
    prep_weights_kernel<<<512, 256>>>(W_dec_att, b_dec_att, W_beta, b_beta,
                                      W_ih, W_hh, b_ih, b_hh,
                                      W_init_h, b_init_h, W_init_c, b_init_c);
    build_list_kernel<<<1, 64>>>(lens);
    zerofill_kernel<<<B_ * T_, 256>>>(lens, out);
    meanenc_kernel<<<4096, 256>>>(EO);
    gemm64_kernel<<<dim3(16, 1), 256>>>(meanenc, 512, Winit, 512, binit,
                                        state, 1024, 512);

    // att1 = enc @ W_enc_att^T + b (fp32, reads EO transposed during staging)
    att1_gemm_kernel<<<dim3(4, 128), 256>>>(EO, W_enc_att, b_enc_att);

    // ---- full decode recurrence in ONE persistent kernel ----
    step_kernel<<<NB_, 256, STEP_SMEM>>>(EO, emb, caps, w_full, b_full);

    // ---- all predictions in one big fp32 GEMM over active rows ----
    fc_gemm_kernel<<<dim3(125, 16), 256>>>(W_fc, b_fc, out);
}